// round 7
// baseline (speedup 1.0000x reference)
#include <cuda_runtime.h>
#include <cstdint>

// Problem constants
#define BATCH 2
#define L_SEQ 2048
#define CDIM  1024
#define HEADS 16
#define HD    64
#define MTOT  (BATCH * L_SEQ)       // 4096
#define THREEC (3 * CDIM)           // 3072
#define INV4  0.3535533905932738f   // 64^-0.25

// ---------------------------------------------------------------------------
// Scratch (device globals; no allocation allowed)
// ---------------------------------------------------------------------------
__device__ __align__(16) float g_qkv[(size_t)MTOT * THREEC];  // 48 MB
__device__ __align__(16) float g_q[(size_t)MTOT * CDIM];      // [B,H,L,D]
__device__ __align__(16) float g_k[(size_t)MTOT * CDIM];
__device__ __align__(16) float g_v[(size_t)MTOT * CDIM];
__device__ __align__(16) float g_att[(size_t)MTOT * CDIM];    // [B,L,H*D], tf32-rounded
__device__ __align__(16) float g_xr[(size_t)MTOT * CDIM];     // x, tf32-rounded
__device__ __align__(16) float g_wr[(size_t)CDIM * THREEC];   // w_qkv, tf32-rounded
__device__ __align__(16) float g_wor[(size_t)CDIM * CDIM];    // w_out, tf32-rounded

// ---------------------------------------------------------------------------
// Helpers
// ---------------------------------------------------------------------------
__device__ __forceinline__ uint32_t f2tf32(float f) {
    uint32_t r;
    asm("cvt.rna.tf32.f32 %0, %1;" : "=r"(r) : "f"(f));
    return r;
}

__device__ __forceinline__ void mma_tf32(float* d,
                                         uint32_t a0, uint32_t a1, uint32_t a2, uint32_t a3,
                                         uint32_t b0, uint32_t b1) {
    asm volatile(
        "mma.sync.aligned.m16n8k8.row.col.f32.tf32.tf32.f32 "
        "{%0,%1,%2,%3}, {%4,%5,%6,%7}, {%8,%9}, {%0,%1,%2,%3};\n"
        : "+f"(d[0]), "+f"(d[1]), "+f"(d[2]), "+f"(d[3])
        : "r"(a0), "r"(a1), "r"(a2), "r"(a3), "r"(b0), "r"(b1));
}

// pair-permutation within each 8-col group: maps (t, t+4) -> (2t, 2t+1)
__device__ __forceinline__ int pair_perm(int c) {
    return (c & ~7) | (((c & 3) << 1) | ((c >> 2) & 1));
}

// ---------------------------------------------------------------------------
// tf32 pre-rounding pass
// ---------------------------------------------------------------------------
__global__ __launch_bounds__(256) void round_tf32_kernel(
    const float* __restrict__ src, float* __restrict__ dst, int n4)
{
    int i = blockIdx.x * blockDim.x + threadIdx.x;
    if (i < n4) {
        float4 v = ((const float4*)src)[i];
        v.x = __uint_as_float(f2tf32(v.x));
        v.y = __uint_as_float(f2tf32(v.y));
        v.z = __uint_as_float(f2tf32(v.z));
        v.w = __uint_as_float(f2tf32(v.w));
        ((float4*)dst)[i] = v;
    }
}

// ---------------------------------------------------------------------------
// Attention-style TF32 GEMM: C[M,N] = A[M,K]*B[K,N]
// BM=BN=128, BK=64 chunk. 256 threads, 8 warps, each 16 rows x 128 cols.
// As: [m][perm(k)] stride 72 (= attention Qs layout)
// Bs: [n][perm(k)] stride 72, filled by transposed store (= attention Vt)
// Inputs pre-rounded to tf32. Smem: 2*128*72*4 = 73,728 B -> 2 CTAs/SM.
// ---------------------------------------------------------------------------
#define TG_STR 72
#define TG_SMEM_BYTES (2 * 128 * TG_STR * 4)

__global__ __launch_bounds__(256, 2) void gemm_as_kernel(
    const float* __restrict__ A, const float* __restrict__ B,
    float* __restrict__ C, int M, int N, int K)
{
    extern __shared__ float sm[];
    float* As = sm;                 // [128][72]  m rows, perm(k) cols
    float* Bs = sm + 128 * TG_STR;  // [128][72]  n rows, perm(k) cols

    const int tid  = threadIdx.x;
    const int w    = tid >> 5;
    const int lane = tid & 31;
    const int g = lane >> 2;
    const int t = lane & 3;
    const int m0 = blockIdx.y * 128;
    const int n0 = blockIdx.x * 128;
    const int wr0 = w * 16;         // warp's row base within tile

    float acc[16][4];
#pragma unroll
    for (int nn = 0; nn < 16; nn++)
#pragma unroll
        for (int v = 0; v < 4; v++) acc[nn][v] = 0.f;

    for (int k0 = 0; k0 < K; k0 += 64) {
        __syncthreads();
        // A tile: 128 rows x 64 k, coalesced float4 loads, perm stores
#pragma unroll
        for (int i = 0; i < 8; i++) {
            int idx = tid + i * 256;
            int r  = idx >> 4;
            int k4 = (idx & 15) << 2;
            float4 v = *(const float4*)&A[(size_t)(m0 + r) * K + k0 + k4];
            As[r * TG_STR + pair_perm(k4 + 0)] = v.x;
            As[r * TG_STR + pair_perm(k4 + 1)] = v.y;
            As[r * TG_STR + pair_perm(k4 + 2)] = v.z;
            As[r * TG_STR + pair_perm(k4 + 3)] = v.w;
        }
        // B tile transposed: gmem [k][n] -> smem [n][perm(k)]
        // (attention Vt pattern: lanes take consecutive k rows -> conflict-free STS)
#pragma unroll
        for (int i = 0; i < 8; i++) {
            int idx = tid + i * 256;
            int kr = idx & 63;              // k row 0..63
            int ng = (idx >> 6) << 2;       // n group 0,4,...,124
            float4 v = *(const float4*)&B[(size_t)(k0 + kr) * N + n0 + ng];
            int pk = pair_perm(kr);
            Bs[(ng + 0) * TG_STR + pk] = v.x;
            Bs[(ng + 1) * TG_STR + pk] = v.y;
            Bs[(ng + 2) * TG_STR + pk] = v.z;
            Bs[(ng + 3) * TG_STR + pk] = v.w;
        }
        __syncthreads();

        // compute: kk outer (A frags), nn inner (B frags one LDS.64 each)
#pragma unroll
        for (int kk = 0; kk < 8; kk++) {
            float2 a02 = *(const float2*)&As[(wr0 + g)     * TG_STR + kk * 8 + 2 * t];
            float2 a13 = *(const float2*)&As[(wr0 + g + 8) * TG_STR + kk * 8 + 2 * t];
            uint32_t a0 = __float_as_uint(a02.x);
            uint32_t a1 = __float_as_uint(a13.x);
            uint32_t a2 = __float_as_uint(a02.y);
            uint32_t a3 = __float_as_uint(a13.y);
#pragma unroll
            for (int nn = 0; nn < 16; nn++) {
                float2 b = *(const float2*)&Bs[(nn * 8 + g) * TG_STR + kk * 8 + 2 * t];
                mma_tf32(acc[nn], a0, a1, a2, a3,
                         __float_as_uint(b.x), __float_as_uint(b.y));
            }
        }
    }

    // epilogue
    const int row0 = m0 + wr0 + g;
    const int row1 = row0 + 8;
#pragma unroll
    for (int nn = 0; nn < 16; nn++) {
        const int col = n0 + nn * 8 + 2 * t;
        *(float2*)&C[(size_t)row0 * N + col] = make_float2(acc[nn][0], acc[nn][1]);
        *(float2*)&C[(size_t)row1 * N + col] = make_float2(acc[nn][2], acc[nn][3]);
    }
}

// ---------------------------------------------------------------------------
// LayerNorm(q,k)*D^-0.25 + split; outputs tf32-rounded
// ---------------------------------------------------------------------------
__global__ __launch_bounds__(256) void ln_split_kernel(
    const float* __restrict__ qkv,
    const float* __restrict__ q_scale, const float* __restrict__ q_bias,
    const float* __restrict__ k_scale, const float* __restrict__ k_bias,
    float* __restrict__ q_t, float* __restrict__ k_t, float* __restrict__ v_t)
{
    const int wid  = (blockIdx.x * blockDim.x + threadIdx.x) >> 5;
    const int lane = threadIdx.x & 31;
    const int h = wid & (HEADS - 1);
    const int m = wid >> 4;
    const int b = m >> 11;
    const int l = m & (L_SEQ - 1);

    const float* row = qkv + (size_t)m * THREEC;
    const size_t obase = (((size_t)(b * HEADS + h)) * L_SEQ + l) * HD;

    {
        float x0 = row[h * HD + lane];
        float x1 = row[h * HD + lane + 32];
        float s = x0 + x1;
#pragma unroll
        for (int o = 16; o > 0; o >>= 1) s += __shfl_xor_sync(0xffffffffu, s, o);
        float mu = s * (1.f / HD);
        float d0 = x0 - mu, d1 = x1 - mu;
        float vs = d0 * d0 + d1 * d1;
#pragma unroll
        for (int o = 16; o > 0; o >>= 1) vs += __shfl_xor_sync(0xffffffffu, vs, o);
        float rstd = rsqrtf(vs * (1.f / HD) + 1e-6f);
        q_t[obase + lane] =
            __uint_as_float(f2tf32((d0 * rstd * q_scale[lane] + q_bias[lane]) * INV4));
        q_t[obase + lane + 32] =
            __uint_as_float(f2tf32((d1 * rstd * q_scale[lane + 32] + q_bias[lane + 32]) * INV4));
    }
    {
        float x0 = row[CDIM + h * HD + lane];
        float x1 = row[CDIM + h * HD + lane + 32];
        float s = x0 + x1;
#pragma unroll
        for (int o = 16; o > 0; o >>= 1) s += __shfl_xor_sync(0xffffffffu, s, o);
        float mu = s * (1.f / HD);
        float d0 = x0 - mu, d1 = x1 - mu;
        float vs = d0 * d0 + d1 * d1;
#pragma unroll
        for (int o = 16; o > 0; o >>= 1) vs += __shfl_xor_sync(0xffffffffu, vs, o);
        float rstd = rsqrtf(vs * (1.f / HD) + 1e-6f);
        k_t[obase + lane] =
            __uint_as_float(f2tf32((d0 * rstd * k_scale[lane] + k_bias[lane]) * INV4));
        k_t[obase + lane + 32] =
            __uint_as_float(f2tf32((d1 * rstd * k_scale[lane + 32] + k_bias[lane + 32]) * INV4));
    }
    v_t[obase + lane]      = __uint_as_float(f2tf32(row[2 * CDIM + h * HD + lane]));
    v_t[obase + lane + 32] = __uint_as_float(f2tf32(row[2 * CDIM + h * HD + lane + 32]));
}

// ---------------------------------------------------------------------------
// Flash attention (mma.sync tf32) — unchanged (passing config)
// ---------------------------------------------------------------------------
#define QS_STR 72
#define KS_STR 72
#define VT_STR 72
#define ATTN_SMEM_BYTES ((128 * QS_STR + 64 * KS_STR + 64 * VT_STR) * 4)

__global__ __launch_bounds__(256, 2) void attn_mma_kernel(
    const float* __restrict__ q_t, const float* __restrict__ k_t,
    const float* __restrict__ v_t, float* __restrict__ att)
{
    extern __shared__ float sm[];
    float* Qs = sm;
    float* Ks = sm + 128 * QS_STR;
    float* Vt = sm + 128 * QS_STR + 64 * KS_STR;

    const int tid  = threadIdx.x;
    const int w    = tid >> 5;
    const int lane = tid & 31;
    const int g = lane >> 2;
    const int t = lane & 3;
    const int bh = blockIdx.y;
    const int q0 = blockIdx.x * 128;

    const float* Qp = q_t + (size_t)bh * L_SEQ * HD;
    const float* Kp = k_t + (size_t)bh * L_SEQ * HD;
    const float* Vp = v_t + (size_t)bh * L_SEQ * HD;

#pragma unroll
    for (int i = 0; i < 8; i++) {
        int idx = tid + i * 256;
        int r  = idx >> 4;
        int d4 = (idx & 15) << 2;
        float4 qv = *(const float4*)&Qp[(size_t)(q0 + r) * HD + d4];
        Qs[r * QS_STR + pair_perm(d4 + 0)] = qv.x;
        Qs[r * QS_STR + pair_perm(d4 + 1)] = qv.y;
        Qs[r * QS_STR + pair_perm(d4 + 2)] = qv.z;
        Qs[r * QS_STR + pair_perm(d4 + 3)] = qv.w;
    }

    float o[8][4];
#pragma unroll
    for (int nn = 0; nn < 8; nn++)
#pragma unroll
        for (int v = 0; v < 4; v++) o[nn][v] = 0.f;
    float mrow0 = -1e30f, mrow1 = -1e30f;
    float lrow0 = 0.f,    lrow1 = 0.f;

    const int qr0 = w * 16;

    for (int kt = 0; kt < L_SEQ; kt += 64) {
        __syncthreads();
#pragma unroll
        for (int i = 0; i < 4; i++) {
            int idx = tid + i * 256;
            int key = idx >> 4;
            int d4  = (idx & 15) << 2;
            float4 kv = *(const float4*)&Kp[(size_t)(kt + key) * HD + d4];
            Ks[key * KS_STR + pair_perm(d4 + 0)] = kv.x;
            Ks[key * KS_STR + pair_perm(d4 + 1)] = kv.y;
            Ks[key * KS_STR + pair_perm(d4 + 2)] = kv.z;
            Ks[key * KS_STR + pair_perm(d4 + 3)] = kv.w;
        }
#pragma unroll
        for (int i = 0; i < 4; i++) {
            int idx = tid + i * 256;
            int key = idx & 63;
            int dg  = (idx >> 6) << 2;
            float4 vv = *(const float4*)&Vp[(size_t)(kt + key) * HD + dg];
            int pk = pair_perm(key);
            Vt[(dg + 0) * VT_STR + pk] = vv.x;
            Vt[(dg + 1) * VT_STR + pk] = vv.y;
            Vt[(dg + 2) * VT_STR + pk] = vv.z;
            Vt[(dg + 3) * VT_STR + pk] = vv.w;
        }
        __syncthreads();

        float s[8][4];
#pragma unroll
        for (int nn = 0; nn < 8; nn++)
#pragma unroll
            for (int v = 0; v < 4; v++) s[nn][v] = 0.f;

#pragma unroll
        for (int kk = 0; kk < 8; kk++) {
            float2 qa02 = *(const float2*)&Qs[(qr0 + g)     * QS_STR + kk * 8 + 2 * t];
            float2 qa13 = *(const float2*)&Qs[(qr0 + g + 8) * QS_STR + kk * 8 + 2 * t];
            uint32_t a0 = __float_as_uint(qa02.x);
            uint32_t a1 = __float_as_uint(qa13.x);
            uint32_t a2 = __float_as_uint(qa02.y);
            uint32_t a3 = __float_as_uint(qa13.y);
#pragma unroll
            for (int nn = 0; nn < 8; nn++) {
                float2 b = *(const float2*)&Ks[(nn * 8 + g) * KS_STR + kk * 8 + 2 * t];
                mma_tf32(s[nn], a0, a1, a2, a3,
                         __float_as_uint(b.x), __float_as_uint(b.y));
            }
        }

        float mx0 = -1e30f, mx1 = -1e30f;
#pragma unroll
        for (int nn = 0; nn < 8; nn++) {
            mx0 = fmaxf(mx0, fmaxf(s[nn][0], s[nn][1]));
            mx1 = fmaxf(mx1, fmaxf(s[nn][2], s[nn][3]));
        }
        mx0 = fmaxf(mx0, __shfl_xor_sync(0xffffffffu, mx0, 1));
        mx0 = fmaxf(mx0, __shfl_xor_sync(0xffffffffu, mx0, 2));
        mx1 = fmaxf(mx1, __shfl_xor_sync(0xffffffffu, mx1, 1));
        mx1 = fmaxf(mx1, __shfl_xor_sync(0xffffffffu, mx1, 2));

        float mn0 = fmaxf(mrow0, mx0);
        float mn1 = fmaxf(mrow1, mx1);
        float alpha0 = __expf(mrow0 - mn0);
        float alpha1 = __expf(mrow1 - mn1);
        mrow0 = mn0; mrow1 = mn1;

        float rs0 = 0.f, rs1 = 0.f;
#pragma unroll
        for (int nn = 0; nn < 8; nn++) {
            float p0 = __expf(s[nn][0] - mn0);
            float p1 = __expf(s[nn][1] - mn0);
            float p2 = __expf(s[nn][2] - mn1);
            float p3 = __expf(s[nn][3] - mn1);
            rs0 += p0 + p1;
            rs1 += p2 + p3;
            s[nn][0] = __uint_as_float(f2tf32(p0));
            s[nn][1] = __uint_as_float(f2tf32(p1));
            s[nn][2] = __uint_as_float(f2tf32(p2));
            s[nn][3] = __uint_as_float(f2tf32(p3));
        }
        rs0 += __shfl_xor_sync(0xffffffffu, rs0, 1);
        rs0 += __shfl_xor_sync(0xffffffffu, rs0, 2);
        rs1 += __shfl_xor_sync(0xffffffffu, rs1, 1);
        rs1 += __shfl_xor_sync(0xffffffffu, rs1, 2);
        lrow0 = lrow0 * alpha0 + rs0;
        lrow1 = lrow1 * alpha1 + rs1;

#pragma unroll
        for (int nn = 0; nn < 8; nn++) {
            o[nn][0] *= alpha0; o[nn][1] *= alpha0;
            o[nn][2] *= alpha1; o[nn][3] *= alpha1;
        }

        const int srcA = (lane & ~3) | (t >> 1);
        const int srcB = srcA + 2;
#pragma unroll
        for (int kk = 0; kk < 8; kk++) {
            float c0 = s[kk][0], c1 = s[kk][1], c2 = s[kk][2], c3 = s[kk][3];
            float e0  = __shfl_sync(0xffffffffu, c0, srcA);
            float o0_ = __shfl_sync(0xffffffffu, c1, srcA);
            float e0b = __shfl_sync(0xffffffffu, c0, srcB);
            float o0b = __shfl_sync(0xffffffffu, c1, srcB);
            float e1  = __shfl_sync(0xffffffffu, c2, srcA);
            float o1_ = __shfl_sync(0xffffffffu, c3, srcA);
            float e1b = __shfl_sync(0xffffffffu, c2, srcB);
            float o1b = __shfl_sync(0xffffffffu, c3, srcB);
            uint32_t a0 = __float_as_uint((t & 1) ? o0_ : e0);
            uint32_t a1 = __float_as_uint((t & 1) ? o1_ : e1);
            uint32_t a2 = __float_as_uint((t & 1) ? o0b : e0b);
            uint32_t a3 = __float_as_uint((t & 1) ? o1b : e1b);
#pragma unroll
            for (int nn = 0; nn < 8; nn++) {
                float2 b = *(const float2*)&Vt[(nn * 8 + g) * VT_STR + kk * 8 + 2 * t];
                mma_tf32(o[nn], a0, a1, a2, a3,
                         __float_as_uint(b.x), __float_as_uint(b.y));
            }
        }
    }

    const int b_ = bh >> 4;
    const int h  = bh & (HEADS - 1);
    const float inv0 = 1.f / lrow0;
    const float inv1 = 1.f / lrow1;
    const int qrow = q0 + qr0;
    const size_t base0 = ((size_t)b_ * L_SEQ + qrow + g)     * CDIM + h * HD;
    const size_t base1 = ((size_t)b_ * L_SEQ + qrow + g + 8) * CDIM + h * HD;
#pragma unroll
    for (int nn = 0; nn < 8; nn++) {
        float2 v0 = make_float2(__uint_as_float(f2tf32(o[nn][0] * inv0)),
                                __uint_as_float(f2tf32(o[nn][1] * inv0)));
        float2 v1 = make_float2(__uint_as_float(f2tf32(o[nn][2] * inv1)),
                                __uint_as_float(f2tf32(o[nn][3] * inv1)));
        *(float2*)&att[base0 + nn * 8 + 2 * t] = v0;
        *(float2*)&att[base1 + nn * 8 + 2 * t] = v1;
    }
}

// ---------------------------------------------------------------------------
// Host launch
// ---------------------------------------------------------------------------
extern "C" void kernel_launch(void* const* d_in, const int* in_sizes, int n_in,
                              void* d_out, int out_size)
{
    const float* x       = (const float*)d_in[0];
    const float* w_qkv   = (const float*)d_in[1];
    const float* w_out   = (const float*)d_in[2];
    const float* q_scale = (const float*)d_in[3];
    const float* q_bias  = (const float*)d_in[4];
    const float* k_scale = (const float*)d_in[5];
    const float* k_bias  = (const float*)d_in[6];
    float* out = (float*)d_out;

    void *p_qkv, *p_q, *p_k, *p_v, *p_att, *p_xr, *p_wr, *p_wor;
    cudaGetSymbolAddress(&p_qkv, g_qkv);
    cudaGetSymbolAddress(&p_q, g_q);
    cudaGetSymbolAddress(&p_k, g_k);
    cudaGetSymbolAddress(&p_v, g_v);
    cudaGetSymbolAddress(&p_att, g_att);
    cudaGetSymbolAddress(&p_xr, g_xr);
    cudaGetSymbolAddress(&p_wr, g_wr);
    cudaGetSymbolAddress(&p_wor, g_wor);

    // 0) pre-round inputs to tf32
    {
        int n4x = MTOT * CDIM / 4;
        int n4w = CDIM * THREEC / 4;
        int n4o = CDIM * CDIM / 4;
        round_tf32_kernel<<<(n4x + 255) / 256, 256>>>(x, (float*)p_xr, n4x);
        round_tf32_kernel<<<(n4w + 255) / 256, 256>>>(w_qkv, (float*)p_wr, n4w);
        round_tf32_kernel<<<(n4o + 255) / 256, 256>>>(w_out, (float*)p_wor, n4o);
    }

    // 1) QKV projection
    cudaFuncSetAttribute(gemm_as_kernel, cudaFuncAttributeMaxDynamicSharedMemorySize,
                         TG_SMEM_BYTES);
    gemm_as_kernel<<<dim3(THREEC / 128, MTOT / 128), 256, TG_SMEM_BYTES>>>(
        (const float*)p_xr, (const float*)p_wr, (float*)p_qkv, MTOT, THREEC, CDIM);

    // 2) QK LayerNorm + head split
    ln_split_kernel<<<(MTOT * HEADS) / 8, 256>>>(
        (const float*)p_qkv, q_scale, q_bias, k_scale, k_bias,
        (float*)p_q, (float*)p_k, (float*)p_v);

    // 3) Flash attention
    cudaFuncSetAttribute(attn_mma_kernel, cudaFuncAttributeMaxDynamicSharedMemorySize,
                         ATTN_SMEM_BYTES);
    attn_mma_kernel<<<dim3(L_SEQ / 128, BATCH * HEADS), 256, ATTN_SMEM_BYTES>>>(
        (const float*)p_q, (const float*)p_k, (const float*)p_v, (float*)p_att);

    // 4) Output projection
    gemm_as_kernel<<<dim3(CDIM / 128, MTOT / 128), 256, TG_SMEM_BYTES>>>(
        (const float*)p_att, (const float*)p_wor, out, MTOT, CDIM, CDIM);
}

// round 9
// speedup vs baseline: 1.4376x; 1.4376x over previous
#include <cuda_runtime.h>
#include <cuda_fp16.h>
#include <cstdint>

// Problem constants
#define BATCH 2
#define L_SEQ 2048
#define CDIM  1024
#define HEADS 16
#define HD    64
#define MTOT  4096
#define THREEC 3072
#define INV4  0.3535533905932738f   // 64^-0.25

// ---------------------------------------------------------------------------
// Scratch (device globals; no allocation allowed)
// ---------------------------------------------------------------------------
__device__ __align__(16) float    g_qkv [(size_t)MTOT * THREEC];  // f32 QKV out
__device__ __align__(16) float    g_q   [(size_t)MTOT * CDIM];    // [B,H,L,D] tf32
__device__ __align__(16) float    g_k   [(size_t)MTOT * CDIM];
__device__ __align__(16) float    g_v   [(size_t)MTOT * CDIM];
__device__ __align__(16) float    g_att [(size_t)MTOT * CDIM];    // attn out f32 [B,L,C]
__device__ __align__(16) uint32_t g_xh  [(size_t)MTOT * 512];     // x half perm16
__device__ __align__(16) uint32_t g_wh  [(size_t)THREEC * 512];   // w_qkv^T half perm16
__device__ __align__(16) uint32_t g_worh[(size_t)CDIM * 512];     // w_out^T half perm16
__device__ __align__(16) uint32_t g_atth[(size_t)MTOT * 512];     // attn out half perm16

// ---------------------------------------------------------------------------
// Helpers
// ---------------------------------------------------------------------------
__device__ __forceinline__ int p16(int c) { return ((c & 3) << 2) | (c >> 2); }

__device__ __forceinline__ uint32_t pack_h2(float a, float b) {
    __half2 h = __floats2half2_rn(a, b);     // low = a, high = b
    return *reinterpret_cast<uint32_t*>(&h);
}

__device__ __forceinline__ uint32_t f2tf32(float f) {
    uint32_t r;
    asm("cvt.rna.tf32.f32 %0, %1;" : "=r"(r) : "f"(f));
    return r;
}

__device__ __forceinline__ void mma_h(float* d,
                                      uint32_t a0, uint32_t a1, uint32_t a2, uint32_t a3,
                                      uint32_t b0, uint32_t b1) {
    asm volatile(
        "mma.sync.aligned.m16n8k16.row.col.f32.f16.f16.f32 "
        "{%0,%1,%2,%3}, {%4,%5,%6,%7}, {%8,%9}, {%0,%1,%2,%3};\n"
        : "+f"(d[0]), "+f"(d[1]), "+f"(d[2]), "+f"(d[3])
        : "r"(a0), "r"(a1), "r"(a2), "r"(a3), "r"(b0), "r"(b1));
}

__device__ __forceinline__ void mma_tf32(float* d,
                                         uint32_t a0, uint32_t a1, uint32_t a2, uint32_t a3,
                                         uint32_t b0, uint32_t b1) {
    asm volatile(
        "mma.sync.aligned.m16n8k8.row.col.f32.tf32.tf32.f32 "
        "{%0,%1,%2,%3}, {%4,%5,%6,%7}, {%8,%9}, {%0,%1,%2,%3};\n"
        : "+f"(d[0]), "+f"(d[1]), "+f"(d[2]), "+f"(d[3])
        : "r"(a0), "r"(a1), "r"(a2), "r"(a3), "r"(b0), "r"(b1));
}

__device__ __forceinline__ int pair_perm(int c) {
    return (c & ~7) | (((c & 3) << 1) | ((c >> 2) & 1));
}

// ---------------------------------------------------------------------------
// Prep: f32 [R][1024] -> half u32 [R][512] with perm16 along K
// ---------------------------------------------------------------------------
__global__ __launch_bounds__(256) void cvt_perm_kernel(
    const float* __restrict__ src, uint32_t* __restrict__ dst, int n_f4)
{
    int i = blockIdx.x * blockDim.x + threadIdx.x;
    if (i >= n_f4) return;
    float4 v = ((const float4*)src)[i];
    int row = i >> 8;
    int f4  = i & 255;
    int k2a = 2 * f4, k2b = 2 * f4 + 1;
    int base = row * 512;
    dst[base + (k2a & ~15) + p16(k2a & 15)] = pack_h2(v.x, v.y);
    dst[base + (k2b & ~15) + p16(k2b & 15)] = pack_h2(v.z, v.w);
}

// f32 [K][C] -> half u32 [C][K/2] (transposed) with perm16 along K
__global__ __launch_bounds__(256) void transpose_cvt_perm_kernel(
    const float* __restrict__ src, uint32_t* __restrict__ dst, int K, int C)
{
    __shared__ float tile[32][33];
    const int c0 = blockIdx.x * 32, k0 = blockIdx.y * 32;
    const int tx = threadIdx.x & 31;
    const int ty = threadIdx.x >> 5;
#pragma unroll
    for (int j = 0; j < 4; j++)
        tile[ty + j * 8][tx] = src[(size_t)(k0 + ty + j * 8) * C + c0 + tx];
    __syncthreads();
#pragma unroll
    for (int j = 0; j < 2; j++) {
        int k2l = ty + 8 * j;
        uint32_t h = pack_h2(tile[2 * k2l][tx], tile[2 * k2l + 1][tx]);
        dst[(size_t)(c0 + tx) * (K / 2) + (k0 >> 1) + p16(k2l)] = h;
    }
}

// ---------------------------------------------------------------------------
// fp16 GEMM: C[M,N](f32) = A[M,K] * Bt[N,K]^T, half u32 perm16, K=1024.
// BM=BN=128, chunk 32 u32 (64 halves). 8 warps x (16 rows x 128 cols).
// ---------------------------------------------------------------------------
#define GS 48
#define GEMM_SMEM_BYTES (2 * 128 * GS * 4)

__global__ __launch_bounds__(256, 2) void gemm_h_kernel(
    const uint32_t* __restrict__ A, const uint32_t* __restrict__ Bt,
    float* __restrict__ C, int M, int N)
{
    extern __shared__ uint32_t us[];
    uint32_t* As = us;
    uint32_t* Bs = us + 128 * GS;

    const int tid  = threadIdx.x;
    const int w    = tid >> 5;
    const int lane = tid & 31;
    const int g = lane >> 2;
    const int t = lane & 3;
    const int m0 = blockIdx.y * 128;
    const int n0 = blockIdx.x * 128;
    const int wr0 = w * 16;
    const int K2 = 512;

    float acc[16][4];
#pragma unroll
    for (int nn = 0; nn < 16; nn++)
#pragma unroll
        for (int v = 0; v < 4; v++) acc[nn][v] = 0.f;

    for (int k0 = 0; k0 < K2; k0 += 32) {
        __syncthreads();
#pragma unroll
        for (int i = 0; i < 4; i++) {
            int id = i * 256 + tid;
            int rr = id >> 3;
            int c4 = (id & 7) * 4;
            *(uint4*)&As[rr * GS + c4] = *(const uint4*)&A[(size_t)(m0 + rr) * K2 + k0 + c4];
            *(uint4*)&Bs[rr * GS + c4] = *(const uint4*)&Bt[(size_t)(n0 + rr) * K2 + k0 + c4];
        }
        __syncthreads();

#pragma unroll
        for (int kp = 0; kp < 2; kp++) {
            uint4 Ag  = *(const uint4*)&As[(wr0 + g)     * GS + kp * 16 + 4 * t];
            uint4 Ag8 = *(const uint4*)&As[(wr0 + g + 8) * GS + kp * 16 + 4 * t];
#pragma unroll
            for (int nn = 0; nn < 16; nn++) {
                uint4 Bv = *(const uint4*)&Bs[(nn * 8 + g) * GS + kp * 16 + 4 * t];
                mma_h(acc[nn], Ag.x, Ag8.x, Ag.y, Ag8.y, Bv.x, Bv.y);
                mma_h(acc[nn], Ag.z, Ag8.z, Ag.w, Ag8.w, Bv.z, Bv.w);
            }
        }
    }

    const int row0 = m0 + wr0 + g;
    const int row1 = row0 + 8;
#pragma unroll
    for (int nn = 0; nn < 16; nn++) {
        const int col = n0 + nn * 8 + 2 * t;
        *(float2*)&C[(size_t)row0 * N + col] = make_float2(acc[nn][0], acc[nn][1]);
        *(float2*)&C[(size_t)row1 * N + col] = make_float2(acc[nn][2], acc[nn][3]);
    }
}

// ---------------------------------------------------------------------------
// LayerNorm(q,k)*D^-0.25 + split; outputs tf32-rounded (R4 verbatim)
// ---------------------------------------------------------------------------
__global__ __launch_bounds__(256) void ln_split_kernel(
    const float* __restrict__ qkv,
    const float* __restrict__ q_scale, const float* __restrict__ q_bias,
    const float* __restrict__ k_scale, const float* __restrict__ k_bias,
    float* __restrict__ q_t, float* __restrict__ k_t, float* __restrict__ v_t)
{
    const int wid  = (blockIdx.x * blockDim.x + threadIdx.x) >> 5;
    const int lane = threadIdx.x & 31;
    const int h = wid & (HEADS - 1);
    const int m = wid >> 4;
    const int b = m >> 11;
    const int l = m & (L_SEQ - 1);

    const float* row = qkv + (size_t)m * THREEC;
    const size_t obase = (((size_t)(b * HEADS + h)) * L_SEQ + l) * HD;

    {
        float x0 = row[h * HD + lane];
        float x1 = row[h * HD + lane + 32];
        float s = x0 + x1;
#pragma unroll
        for (int o = 16; o > 0; o >>= 1) s += __shfl_xor_sync(0xffffffffu, s, o);
        float mu = s * (1.f / HD);
        float d0 = x0 - mu, d1 = x1 - mu;
        float vs = d0 * d0 + d1 * d1;
#pragma unroll
        for (int o = 16; o > 0; o >>= 1) vs += __shfl_xor_sync(0xffffffffu, vs, o);
        float rstd = rsqrtf(vs * (1.f / HD) + 1e-6f);
        q_t[obase + lane] =
            __uint_as_float(f2tf32((d0 * rstd * q_scale[lane] + q_bias[lane]) * INV4));
        q_t[obase + lane + 32] =
            __uint_as_float(f2tf32((d1 * rstd * q_scale[lane + 32] + q_bias[lane + 32]) * INV4));
    }
    {
        float x0 = row[CDIM + h * HD + lane];
        float x1 = row[CDIM + h * HD + lane + 32];
        float s = x0 + x1;
#pragma unroll
        for (int o = 16; o > 0; o >>= 1) s += __shfl_xor_sync(0xffffffffu, s, o);
        float mu = s * (1.f / HD);
        float d0 = x0 - mu, d1 = x1 - mu;
        float vs = d0 * d0 + d1 * d1;
#pragma unroll
        for (int o = 16; o > 0; o >>= 1) vs += __shfl_xor_sync(0xffffffffu, vs, o);
        float rstd = rsqrtf(vs * (1.f / HD) + 1e-6f);
        k_t[obase + lane] =
            __uint_as_float(f2tf32((d0 * rstd * k_scale[lane] + k_bias[lane]) * INV4));
        k_t[obase + lane + 32] =
            __uint_as_float(f2tf32((d1 * rstd * k_scale[lane + 32] + k_bias[lane + 32]) * INV4));
    }
    v_t[obase + lane]      = __uint_as_float(f2tf32(row[2 * CDIM + h * HD + lane]));
    v_t[obase + lane + 32] = __uint_as_float(f2tf32(row[2 * CDIM + h * HD + lane + 32]));
}

// ---------------------------------------------------------------------------
// Flash attention (mma.sync tf32) — R4 verbatim (passing config)
// ---------------------------------------------------------------------------
#define QS_STR 72
#define KS_STR 72
#define VT_STR 72
#define ATTN_SMEM_BYTES ((128 * QS_STR + 64 * KS_STR + 64 * VT_STR) * 4)

__global__ __launch_bounds__(256, 2) void attn_mma_kernel(
    const float* __restrict__ q_t, const float* __restrict__ k_t,
    const float* __restrict__ v_t, float* __restrict__ att)
{
    extern __shared__ float sm[];
    float* Qs = sm;
    float* Ks = sm + 128 * QS_STR;
    float* Vt = sm + 128 * QS_STR + 64 * KS_STR;

    const int tid  = threadIdx.x;
    const int w    = tid >> 5;
    const int lane = tid & 31;
    const int g = lane >> 2;
    const int t = lane & 3;
    const int bh = blockIdx.y;
    const int q0 = blockIdx.x * 128;

    const float* Qp = q_t + (size_t)bh * L_SEQ * HD;
    const float* Kp = k_t + (size_t)bh * L_SEQ * HD;
    const float* Vp = v_t + (size_t)bh * L_SEQ * HD;

#pragma unroll
    for (int i = 0; i < 8; i++) {
        int idx = tid + i * 256;
        int r  = idx >> 4;
        int d4 = (idx & 15) << 2;
        float4 qv = *(const float4*)&Qp[(size_t)(q0 + r) * HD + d4];
        Qs[r * QS_STR + pair_perm(d4 + 0)] = qv.x;
        Qs[r * QS_STR + pair_perm(d4 + 1)] = qv.y;
        Qs[r * QS_STR + pair_perm(d4 + 2)] = qv.z;
        Qs[r * QS_STR + pair_perm(d4 + 3)] = qv.w;
    }

    float o[8][4];
#pragma unroll
    for (int nn = 0; nn < 8; nn++)
#pragma unroll
        for (int v = 0; v < 4; v++) o[nn][v] = 0.f;
    float mrow0 = -1e30f, mrow1 = -1e30f;
    float lrow0 = 0.f,    lrow1 = 0.f;

    const int qr0 = w * 16;

    for (int kt = 0; kt < L_SEQ; kt += 64) {
        __syncthreads();
#pragma unroll
        for (int i = 0; i < 4; i++) {
            int idx = tid + i * 256;
            int key = idx >> 4;
            int d4  = (idx & 15) << 2;
            float4 kv = *(const float4*)&Kp[(size_t)(kt + key) * HD + d4];
            Ks[key * KS_STR + pair_perm(d4 + 0)] = kv.x;
            Ks[key * KS_STR + pair_perm(d4 + 1)] = kv.y;
            Ks[key * KS_STR + pair_perm(d4 + 2)] = kv.z;
            Ks[key * KS_STR + pair_perm(d4 + 3)] = kv.w;
        }
#pragma unroll
        for (int i = 0; i < 4; i++) {
            int idx = tid + i * 256;
            int key = idx & 63;
            int dg  = (idx >> 6) << 2;
            float4 vv = *(const float4*)&Vp[(size_t)(kt + key) * HD + dg];
            int pk = pair_perm(key);
            Vt[(dg + 0) * VT_STR + pk] = vv.x;
            Vt[(dg + 1) * VT_STR + pk] = vv.y;
            Vt[(dg + 2) * VT_STR + pk] = vv.z;
            Vt[(dg + 3) * VT_STR + pk] = vv.w;
        }
        __syncthreads();

        float s[8][4];
#pragma unroll
        for (int nn = 0; nn < 8; nn++)
#pragma unroll
            for (int v = 0; v < 4; v++) s[nn][v] = 0.f;

#pragma unroll
        for (int kk = 0; kk < 8; kk++) {
            float2 qa02 = *(const float2*)&Qs[(qr0 + g)     * QS_STR + kk * 8 + 2 * t];
            float2 qa13 = *(const float2*)&Qs[(qr0 + g + 8) * QS_STR + kk * 8 + 2 * t];
            uint32_t a0 = __float_as_uint(qa02.x);
            uint32_t a1 = __float_as_uint(qa13.x);
            uint32_t a2 = __float_as_uint(qa02.y);
            uint32_t a3 = __float_as_uint(qa13.y);
#pragma unroll
            for (int nn = 0; nn < 8; nn++) {
                float2 b = *(const float2*)&Ks[(nn * 8 + g) * KS_STR + kk * 8 + 2 * t];
                mma_tf32(s[nn], a0, a1, a2, a3,
                         __float_as_uint(b.x), __float_as_uint(b.y));
            }
        }

        float mx0 = -1e30f, mx1 = -1e30f;
#pragma unroll
        for (int nn = 0; nn < 8; nn++) {
            mx0 = fmaxf(mx0, fmaxf(s[nn][0], s[nn][1]));
            mx1 = fmaxf(mx1, fmaxf(s[nn][2], s[nn][3]));
        }
        mx0 = fmaxf(mx0, __shfl_xor_sync(0xffffffffu, mx0, 1));
        mx0 = fmaxf(mx0, __shfl_xor_sync(0xffffffffu, mx0, 2));
        mx1 = fmaxf(mx1, __shfl_xor_sync(0xffffffffu, mx1, 1));
        mx1 = fmaxf(mx1, __shfl_xor_sync(0xffffffffu, mx1, 2));

        float mn0 = fmaxf(mrow0, mx0);
        float mn1 = fmaxf(mrow1, mx1);
        float alpha0 = __expf(mrow0 - mn0);
        float alpha1 = __expf(mrow1 - mn1);
        mrow0 = mn0; mrow1 = mn1;

        float rs0 = 0.f, rs1 = 0.f;
#pragma unroll
        for (int nn = 0; nn < 8; nn++) {
            float p0 = __expf(s[nn][0] - mn0);
            float p1 = __expf(s[nn][1] - mn0);
            float p2 = __expf(s[nn][2] - mn1);
            float p3 = __expf(s[nn][3] - mn1);
            rs0 += p0 + p1;
            rs1 += p2 + p3;
            s[nn][0] = __uint_as_float(f2tf32(p0));
            s[nn][1] = __uint_as_float(f2tf32(p1));
            s[nn][2] = __uint_as_float(f2tf32(p2));
            s[nn][3] = __uint_as_float(f2tf32(p3));
        }
        rs0 += __shfl_xor_sync(0xffffffffu, rs0, 1);
        rs0 += __shfl_xor_sync(0xffffffffu, rs0, 2);
        rs1 += __shfl_xor_sync(0xffffffffu, rs1, 1);
        rs1 += __shfl_xor_sync(0xffffffffu, rs1, 2);
        lrow0 = lrow0 * alpha0 + rs0;
        lrow1 = lrow1 * alpha1 + rs1;

#pragma unroll
        for (int nn = 0; nn < 8; nn++) {
            o[nn][0] *= alpha0; o[nn][1] *= alpha0;
            o[nn][2] *= alpha1; o[nn][3] *= alpha1;
        }

        const int srcA = (lane & ~3) | (t >> 1);
        const int srcB = srcA + 2;
#pragma unroll
        for (int kk = 0; kk < 8; kk++) {
            float c0 = s[kk][0], c1 = s[kk][1], c2 = s[kk][2], c3 = s[kk][3];
            float e0  = __shfl_sync(0xffffffffu, c0, srcA);
            float o0_ = __shfl_sync(0xffffffffu, c1, srcA);
            float e0b = __shfl_sync(0xffffffffu, c0, srcB);
            float o0b = __shfl_sync(0xffffffffu, c1, srcB);
            float e1  = __shfl_sync(0xffffffffu, c2, srcA);
            float o1_ = __shfl_sync(0xffffffffu, c3, srcA);
            float e1b = __shfl_sync(0xffffffffu, c2, srcB);
            float o1b = __shfl_sync(0xffffffffu, c3, srcB);
            uint32_t a0 = __float_as_uint((t & 1) ? o0_ : e0);
            uint32_t a1 = __float_as_uint((t & 1) ? o1_ : e1);
            uint32_t a2 = __float_as_uint((t & 1) ? o0b : e0b);
            uint32_t a3 = __float_as_uint((t & 1) ? o1b : e1b);
#pragma unroll
            for (int nn = 0; nn < 8; nn++) {
                float2 b = *(const float2*)&Vt[(nn * 8 + g) * VT_STR + kk * 8 + 2 * t];
                mma_tf32(o[nn], a0, a1, a2, a3,
                         __float_as_uint(b.x), __float_as_uint(b.y));
            }
        }
    }

    const int b_ = bh >> 4;
    const int h  = bh & (HEADS - 1);
    const float inv0 = 1.f / lrow0;
    const float inv1 = 1.f / lrow1;
    const int qrow = q0 + qr0;
    const size_t base0 = ((size_t)b_ * L_SEQ + qrow + g)     * CDIM + h * HD;
    const size_t base1 = ((size_t)b_ * L_SEQ + qrow + g + 8) * CDIM + h * HD;
#pragma unroll
    for (int nn = 0; nn < 8; nn++) {
        *(float2*)&att[base0 + nn * 8 + 2 * t] = make_float2(o[nn][0] * inv0, o[nn][1] * inv0);
        *(float2*)&att[base1 + nn * 8 + 2 * t] = make_float2(o[nn][2] * inv1, o[nn][3] * inv1);
    }
}

// ---------------------------------------------------------------------------
// Host launch
// ---------------------------------------------------------------------------
extern "C" void kernel_launch(void* const* d_in, const int* in_sizes, int n_in,
                              void* d_out, int out_size)
{
    const float* x       = (const float*)d_in[0];
    const float* w_qkv   = (const float*)d_in[1];
    const float* w_out   = (const float*)d_in[2];
    const float* q_scale = (const float*)d_in[3];
    const float* q_bias  = (const float*)d_in[4];
    const float* k_scale = (const float*)d_in[5];
    const float* k_bias  = (const float*)d_in[6];
    float* out = (float*)d_out;

    void *p_qkv, *p_q, *p_k, *p_v, *p_att, *p_xh, *p_wh, *p_worh, *p_atth;
    cudaGetSymbolAddress(&p_qkv, g_qkv);
    cudaGetSymbolAddress(&p_q, g_q);
    cudaGetSymbolAddress(&p_k, g_k);
    cudaGetSymbolAddress(&p_v, g_v);
    cudaGetSymbolAddress(&p_att, g_att);
    cudaGetSymbolAddress(&p_xh, g_xh);
    cudaGetSymbolAddress(&p_wh, g_wh);
    cudaGetSymbolAddress(&p_worh, g_worh);
    cudaGetSymbolAddress(&p_atth, g_atth);

    // 0) prep: x -> half perm16; weights -> transposed half perm16
    cvt_perm_kernel<<<(MTOT * 256 + 255) / 256, 256>>>(x, (uint32_t*)p_xh, MTOT * 256);
    transpose_cvt_perm_kernel<<<dim3(THREEC / 32, CDIM / 32), 256>>>(
        w_qkv, (uint32_t*)p_wh, CDIM, THREEC);
    transpose_cvt_perm_kernel<<<dim3(CDIM / 32, CDIM / 32), 256>>>(
        w_out, (uint32_t*)p_worh, CDIM, CDIM);

    // 1) QKV projection (fp16 tensor cores)
    cudaFuncSetAttribute(gemm_h_kernel, cudaFuncAttributeMaxDynamicSharedMemorySize,
                         GEMM_SMEM_BYTES);
    gemm_h_kernel<<<dim3(THREEC / 128, MTOT / 128), 256, GEMM_SMEM_BYTES>>>(
        (const uint32_t*)p_xh, (const uint32_t*)p_wh, (float*)p_qkv, MTOT, THREEC);

    // 2) QK LayerNorm + head split (tf32, R4)
    ln_split_kernel<<<(MTOT * HEADS) / 8, 256>>>(
        (const float*)p_qkv, q_scale, q_bias, k_scale, k_bias,
        (float*)p_q, (float*)p_k, (float*)p_v);

    // 3) Flash attention (tf32, R4) -> f32 natural layout
    cudaFuncSetAttribute(attn_mma_kernel, cudaFuncAttributeMaxDynamicSharedMemorySize,
                         ATTN_SMEM_BYTES);
    attn_mma_kernel<<<dim3(L_SEQ / 128, BATCH * HEADS), 256, ATTN_SMEM_BYTES>>>(
        (const float*)p_q, (const float*)p_k, (const float*)p_v, (float*)p_att);

    // 3b) convert attention output to half perm16
    cvt_perm_kernel<<<(MTOT * 256 + 255) / 256, 256>>>(
        (const float*)p_att, (uint32_t*)p_atth, MTOT * 256);

    // 4) Output projection (fp16 tensor cores)
    gemm_h_kernel<<<dim3(CDIM / 128, MTOT / 128), 256, GEMM_SMEM_BYTES>>>(
        (const uint32_t*)p_atth, (const uint32_t*)p_worh, out, MTOT, CDIM);
}

// round 10
// speedup vs baseline: 1.8476x; 1.2853x over previous
#include <cuda_runtime.h>
#include <cuda_fp16.h>
#include <cstdint>

// Problem constants
#define BATCH 2
#define L_SEQ 2048
#define CDIM  1024
#define HEADS 16
#define HD    64
#define MTOT  4096
#define THREEC 3072
#define INV4  0.3535533905932738f   // 64^-0.25

// ---------------------------------------------------------------------------
// Scratch (device globals; no allocation allowed)
// ---------------------------------------------------------------------------
__device__ __align__(16) float    g_qkv [(size_t)MTOT * THREEC];  // f32 QKV out
__device__ __align__(16) float    g_q   [(size_t)MTOT * CDIM];    // [B,H,L,D] tf32
__device__ __align__(16) float    g_k   [(size_t)MTOT * CDIM];
__device__ __align__(16) float    g_v   [(size_t)MTOT * CDIM];
__device__ __align__(16) float    g_att [(size_t)MTOT * CDIM];    // attn out f32 [B,L,C]
__device__ __align__(16) uint32_t g_xh  [(size_t)MTOT * 512];     // x half perm16
__device__ __align__(16) uint32_t g_wh  [(size_t)THREEC * 512];   // w_qkv^T half perm16
__device__ __align__(16) uint32_t g_worh[(size_t)CDIM * 512];     // w_out^T half perm16
__device__ __align__(16) uint32_t g_atth[(size_t)MTOT * 512];     // attn out half perm16

// ---------------------------------------------------------------------------
// Helpers
// ---------------------------------------------------------------------------
__device__ __forceinline__ int p16(int c) { return ((c & 3) << 2) | (c >> 2); }

__device__ __forceinline__ uint32_t pack_h2(float a, float b) {
    __half2 h = __floats2half2_rn(a, b);     // low = a, high = b
    return *reinterpret_cast<uint32_t*>(&h);
}

__device__ __forceinline__ uint32_t f2tf32(float f) {
    uint32_t r;
    asm("cvt.rna.tf32.f32 %0, %1;" : "=r"(r) : "f"(f));
    return r;
}

__device__ __forceinline__ void mma_h(float* d,
                                      uint32_t a0, uint32_t a1, uint32_t a2, uint32_t a3,
                                      uint32_t b0, uint32_t b1) {
    asm volatile(
        "mma.sync.aligned.m16n8k16.row.col.f32.f16.f16.f32 "
        "{%0,%1,%2,%3}, {%4,%5,%6,%7}, {%8,%9}, {%0,%1,%2,%3};\n"
        : "+f"(d[0]), "+f"(d[1]), "+f"(d[2]), "+f"(d[3])
        : "r"(a0), "r"(a1), "r"(a2), "r"(a3), "r"(b0), "r"(b1));
}

// ---------------------------------------------------------------------------
// Prep: f32 [R][1024] -> half u32 [R][512] with perm16 along K (R9-validated)
// ---------------------------------------------------------------------------
__global__ __launch_bounds__(256) void cvt_perm_kernel(
    const float* __restrict__ src, uint32_t* __restrict__ dst, int n_f4)
{
    int i = blockIdx.x * blockDim.x + threadIdx.x;
    if (i >= n_f4) return;
    float4 v = ((const float4*)src)[i];
    int row = i >> 8;
    int f4  = i & 255;
    int k2a = 2 * f4, k2b = 2 * f4 + 1;
    int base = row * 512;
    dst[base + (k2a & ~15) + p16(k2a & 15)] = pack_h2(v.x, v.y);
    dst[base + (k2b & ~15) + p16(k2b & 15)] = pack_h2(v.z, v.w);
}

// f32 [K][C] -> half u32 [C][K/2] (transposed) with perm16 along K (R9-validated)
__global__ __launch_bounds__(256) void transpose_cvt_perm_kernel(
    const float* __restrict__ src, uint32_t* __restrict__ dst, int K, int C)
{
    __shared__ float tile[32][33];
    const int c0 = blockIdx.x * 32, k0 = blockIdx.y * 32;
    const int tx = threadIdx.x & 31;
    const int ty = threadIdx.x >> 5;
#pragma unroll
    for (int j = 0; j < 4; j++)
        tile[ty + j * 8][tx] = src[(size_t)(k0 + ty + j * 8) * C + c0 + tx];
    __syncthreads();
#pragma unroll
    for (int j = 0; j < 2; j++) {
        int k2l = ty + 8 * j;
        uint32_t h = pack_h2(tile[2 * k2l][tx], tile[2 * k2l + 1][tx]);
        dst[(size_t)(c0 + tx) * (K / 2) + (k0 >> 1) + p16(k2l)] = h;
    }
}

// ---------------------------------------------------------------------------
// fp16 GEMM (R9-validated): C[M,N](f32) = A[M,K] * Bt[N,K]^T, perm16, K=1024.
// ---------------------------------------------------------------------------
#define GS 48
#define GEMM_SMEM_BYTES (2 * 128 * GS * 4)

__global__ __launch_bounds__(256, 2) void gemm_h_kernel(
    const uint32_t* __restrict__ A, const uint32_t* __restrict__ Bt,
    float* __restrict__ C, int M, int N)
{
    extern __shared__ uint32_t us[];
    uint32_t* As = us;
    uint32_t* Bs = us + 128 * GS;

    const int tid  = threadIdx.x;
    const int w    = tid >> 5;
    const int lane = tid & 31;
    const int g = lane >> 2;
    const int t = lane & 3;
    const int m0 = blockIdx.y * 128;
    const int n0 = blockIdx.x * 128;
    const int wr0 = w * 16;
    const int K2 = 512;

    float acc[16][4];
#pragma unroll
    for (int nn = 0; nn < 16; nn++)
#pragma unroll
        for (int v = 0; v < 4; v++) acc[nn][v] = 0.f;

    for (int k0 = 0; k0 < K2; k0 += 32) {
        __syncthreads();
#pragma unroll
        for (int i = 0; i < 4; i++) {
            int id = i * 256 + tid;
            int rr = id >> 3;
            int c4 = (id & 7) * 4;
            *(uint4*)&As[rr * GS + c4] = *(const uint4*)&A[(size_t)(m0 + rr) * K2 + k0 + c4];
            *(uint4*)&Bs[rr * GS + c4] = *(const uint4*)&Bt[(size_t)(n0 + rr) * K2 + k0 + c4];
        }
        __syncthreads();

#pragma unroll
        for (int kp = 0; kp < 2; kp++) {
            uint4 Ag  = *(const uint4*)&As[(wr0 + g)     * GS + kp * 16 + 4 * t];
            uint4 Ag8 = *(const uint4*)&As[(wr0 + g + 8) * GS + kp * 16 + 4 * t];
#pragma unroll
            for (int nn = 0; nn < 16; nn++) {
                uint4 Bv = *(const uint4*)&Bs[(nn * 8 + g) * GS + kp * 16 + 4 * t];
                mma_h(acc[nn], Ag.x, Ag8.x, Ag.y, Ag8.y, Bv.x, Bv.y);
                mma_h(acc[nn], Ag.z, Ag8.z, Ag.w, Ag8.w, Bv.z, Bv.w);
            }
        }
    }

    const int row0 = m0 + wr0 + g;
    const int row1 = row0 + 8;
#pragma unroll
    for (int nn = 0; nn < 16; nn++) {
        const int col = n0 + nn * 8 + 2 * t;
        *(float2*)&C[(size_t)row0 * N + col] = make_float2(acc[nn][0], acc[nn][1]);
        *(float2*)&C[(size_t)row1 * N + col] = make_float2(acc[nn][2], acc[nn][3]);
    }
}

// ---------------------------------------------------------------------------
// LayerNorm(q,k)*D^-0.25 + split; outputs tf32-rounded f32 (R4 verbatim)
// ---------------------------------------------------------------------------
__global__ __launch_bounds__(256) void ln_split_kernel(
    const float* __restrict__ qkv,
    const float* __restrict__ q_scale, const float* __restrict__ q_bias,
    const float* __restrict__ k_scale, const float* __restrict__ k_bias,
    float* __restrict__ q_t, float* __restrict__ k_t, float* __restrict__ v_t)
{
    const int wid  = (blockIdx.x * blockDim.x + threadIdx.x) >> 5;
    const int lane = threadIdx.x & 31;
    const int h = wid & (HEADS - 1);
    const int m = wid >> 4;
    const int b = m >> 11;
    const int l = m & (L_SEQ - 1);

    const float* row = qkv + (size_t)m * THREEC;
    const size_t obase = (((size_t)(b * HEADS + h)) * L_SEQ + l) * HD;

    {
        float x0 = row[h * HD + lane];
        float x1 = row[h * HD + lane + 32];
        float s = x0 + x1;
#pragma unroll
        for (int o = 16; o > 0; o >>= 1) s += __shfl_xor_sync(0xffffffffu, s, o);
        float mu = s * (1.f / HD);
        float d0 = x0 - mu, d1 = x1 - mu;
        float vs = d0 * d0 + d1 * d1;
#pragma unroll
        for (int o = 16; o > 0; o >>= 1) vs += __shfl_xor_sync(0xffffffffu, vs, o);
        float rstd = rsqrtf(vs * (1.f / HD) + 1e-6f);
        q_t[obase + lane] =
            __uint_as_float(f2tf32((d0 * rstd * q_scale[lane] + q_bias[lane]) * INV4));
        q_t[obase + lane + 32] =
            __uint_as_float(f2tf32((d1 * rstd * q_scale[lane + 32] + q_bias[lane + 32]) * INV4));
    }
    {
        float x0 = row[CDIM + h * HD + lane];
        float x1 = row[CDIM + h * HD + lane + 32];
        float s = x0 + x1;
#pragma unroll
        for (int o = 16; o > 0; o >>= 1) s += __shfl_xor_sync(0xffffffffu, s, o);
        float mu = s * (1.f / HD);
        float d0 = x0 - mu, d1 = x1 - mu;
        float vs = d0 * d0 + d1 * d1;
#pragma unroll
        for (int o = 16; o > 0; o >>= 1) vs += __shfl_xor_sync(0xffffffffu, vs, o);
        float rstd = rsqrtf(vs * (1.f / HD) + 1e-6f);
        k_t[obase + lane] =
            __uint_as_float(f2tf32((d0 * rstd * k_scale[lane] + k_bias[lane]) * INV4));
        k_t[obase + lane + 32] =
            __uint_as_float(f2tf32((d1 * rstd * k_scale[lane + 32] + k_bias[lane + 32]) * INV4));
    }
    v_t[obase + lane]      = __uint_as_float(f2tf32(row[2 * CDIM + h * HD + lane]));
    v_t[obase + lane + 32] = __uint_as_float(f2tf32(row[2 * CDIM + h * HD + lane + 32]));
}

// ---------------------------------------------------------------------------
// fp16 flash attention. f32 in (tf32-rounded -> exact fp16 convert), f32 out.
// 128 q-rows/CTA, 8 warps x 16 rows, 64-key tiles.
// Qh[128][GS], Kh[64][GS]: [row][perm16(d2)] half2-u32.
// Vt[64][GS]: [d][perm16(key2)] half2-u32 (key pairs packed).
// smem: 256*GS*4 = 49,152 B.
// ---------------------------------------------------------------------------
#define ATTN_SMEM_BYTES (256 * GS * 4)

__global__ __launch_bounds__(256, 2) void attn_h2_kernel(
    const float* __restrict__ q_t, const float* __restrict__ k_t,
    const float* __restrict__ v_t, float* __restrict__ att)
{
    extern __shared__ uint32_t us[];
    uint32_t* Qh = us;                    // [128][GS]
    uint32_t* Kh = us + 128 * GS;         // [64][GS]
    uint32_t* Vt = us + 192 * GS;         // [64][GS]

    const int tid  = threadIdx.x;
    const int w    = tid >> 5;
    const int lane = tid & 31;
    const int g = lane >> 2;
    const int t = lane & 3;
    const int bh = blockIdx.y;
    const int q0 = blockIdx.x * 128;
    const int qr0 = w * 16;

    const float* Qp = q_t + (size_t)bh * L_SEQ * HD;
    const float* Kp = k_t + (size_t)bh * L_SEQ * HD;
    const float* Vp = v_t + (size_t)bh * L_SEQ * HD;

    // Q tile once: f32 -> fp16 perm16 (exact: inputs are tf32-rounded)
#pragma unroll
    for (int i = 0; i < 8; i++) {
        int idx = tid + i * 256;
        int rr = idx >> 4;
        int j  = idx & 15;
        float4 qv = *(const float4*)&Qp[(size_t)(q0 + rr) * HD + (j << 2)];
        int d2 = j * 2;
        Qh[rr * GS + (d2 & 16) + p16(d2 & 15)]       = pack_h2(qv.x, qv.y);
        Qh[rr * GS + ((d2 + 1) & 16) + p16((d2 + 1) & 15)] = pack_h2(qv.z, qv.w);
    }

    float o[8][4];
#pragma unroll
    for (int nn = 0; nn < 8; nn++)
#pragma unroll
        for (int v = 0; v < 4; v++) o[nn][v] = 0.f;
    float mrow0 = -1e30f, mrow1 = -1e30f;
    float lrow0 = 0.f,    lrow1 = 0.f;

    for (int kt = 0; kt < L_SEQ; kt += 64) {
        __syncthreads();
        // K tile: f32 -> fp16 perm16
#pragma unroll
        for (int i = 0; i < 4; i++) {
            int idx = tid + i * 256;
            int rr = idx >> 4;
            int j  = idx & 15;
            float4 kv = *(const float4*)&Kp[(size_t)(kt + rr) * HD + (j << 2)];
            int d2 = j * 2;
            Kh[rr * GS + (d2 & 16) + p16(d2 & 15)]       = pack_h2(kv.x, kv.y);
            Kh[rr * GS + ((d2 + 1) & 16) + p16((d2 + 1) & 15)] = pack_h2(kv.z, kv.w);
        }
        // V tile transposed + key-pair packed: Vt[d][perm16(key2)]
#pragma unroll
        for (int i = 0; i < 4; i++) {
            int idx = tid + i * 256;
            int key = idx & 63;
            int dg  = (idx >> 6) << 2;
            float4 mv = *(const float4*)&Vp[(size_t)(kt + key) * HD + dg];
            float4 pr;
            pr.x = __shfl_xor_sync(0xffffffffu, mv.x, 1);
            pr.y = __shfl_xor_sync(0xffffffffu, mv.y, 1);
            pr.z = __shfl_xor_sync(0xffffffffu, mv.z, 1);
            pr.w = __shfl_xor_sync(0xffffffffu, mv.w, 1);
            int key2 = key >> 1;
            int pos = (key2 & 16) | p16(key2 & 15);
            if (!(key & 1)) {   // own = even key (low half), partner = odd (high)
                Vt[(dg + 0) * GS + pos] = pack_h2(mv.x, pr.x);
                Vt[(dg + 1) * GS + pos] = pack_h2(mv.y, pr.y);
            } else {            // own = odd key (high half), partner = even (low)
                Vt[(dg + 2) * GS + pos] = pack_h2(pr.z, mv.z);
                Vt[(dg + 3) * GS + pos] = pack_h2(pr.w, mv.w);
            }
        }
        __syncthreads();

        // S = Q K^T (fp16, 32 mma)
        float s[8][4];
#pragma unroll
        for (int nn = 0; nn < 8; nn++)
#pragma unroll
            for (int v = 0; v < 4; v++) s[nn][v] = 0.f;

#pragma unroll
        for (int kp = 0; kp < 2; kp++) {
            uint4 Qg  = *(const uint4*)&Qh[(qr0 + g)     * GS + kp * 16 + 4 * t];
            uint4 Qg8 = *(const uint4*)&Qh[(qr0 + g + 8) * GS + kp * 16 + 4 * t];
#pragma unroll
            for (int nn = 0; nn < 8; nn++) {
                uint4 Kv = *(const uint4*)&Kh[(nn * 8 + g) * GS + kp * 16 + 4 * t];
                mma_h(s[nn], Qg.x, Qg8.x, Qg.y, Qg8.y, Kv.x, Kv.y);
                mma_h(s[nn], Qg.z, Qg8.z, Qg.w, Qg8.w, Kv.z, Kv.w);
            }
        }

        // online softmax (rows g, g+8; quad reductions) — R4 structure
        float mx0 = -1e30f, mx1 = -1e30f;
#pragma unroll
        for (int nn = 0; nn < 8; nn++) {
            mx0 = fmaxf(mx0, fmaxf(s[nn][0], s[nn][1]));
            mx1 = fmaxf(mx1, fmaxf(s[nn][2], s[nn][3]));
        }
        mx0 = fmaxf(mx0, __shfl_xor_sync(0xffffffffu, mx0, 1));
        mx0 = fmaxf(mx0, __shfl_xor_sync(0xffffffffu, mx0, 2));
        mx1 = fmaxf(mx1, __shfl_xor_sync(0xffffffffu, mx1, 1));
        mx1 = fmaxf(mx1, __shfl_xor_sync(0xffffffffu, mx1, 2));

        float mn0 = fmaxf(mrow0, mx0);
        float mn1 = fmaxf(mrow1, mx1);
        float alpha0 = __expf(mrow0 - mn0);
        float alpha1 = __expf(mrow1 - mn1);
        mrow0 = mn0; mrow1 = mn1;

        float rs0 = 0.f, rs1 = 0.f;
#pragma unroll
        for (int nn = 0; nn < 8; nn++) {
            s[nn][0] = __expf(s[nn][0] - mn0);
            s[nn][1] = __expf(s[nn][1] - mn0);
            s[nn][2] = __expf(s[nn][2] - mn1);
            s[nn][3] = __expf(s[nn][3] - mn1);
            rs0 += s[nn][0] + s[nn][1];
            rs1 += s[nn][2] + s[nn][3];
        }
        rs0 += __shfl_xor_sync(0xffffffffu, rs0, 1);
        rs0 += __shfl_xor_sync(0xffffffffu, rs0, 2);
        rs1 += __shfl_xor_sync(0xffffffffu, rs1, 1);
        rs1 += __shfl_xor_sync(0xffffffffu, rs1, 2);
        lrow0 = lrow0 * alpha0 + rs0;
        lrow1 = lrow1 * alpha1 + rs1;

#pragma unroll
        for (int nn = 0; nn < 8; nn++) {
            o[nn][0] *= alpha0; o[nn][1] *= alpha0;
            o[nn][2] *= alpha1; o[nn][3] *= alpha1;
        }

        // O += P V : P C-frags pack directly into A-frags (register-only).
        // A-frag order matches validated gemm_h: (rowg-klo, rowg8-klo, rowg-khi, rowg8-khi)
#pragma unroll
        for (int kp = 0; kp < 2; kp++) {
            uint32_t ae0 = pack_h2(s[4 * kp + 0][0], s[4 * kp + 0][1]);
            uint32_t ae1 = pack_h2(s[4 * kp + 0][2], s[4 * kp + 0][3]);
            uint32_t ae2 = pack_h2(s[4 * kp + 1][0], s[4 * kp + 1][1]);
            uint32_t ae3 = pack_h2(s[4 * kp + 1][2], s[4 * kp + 1][3]);
            uint32_t ao0 = pack_h2(s[4 * kp + 2][0], s[4 * kp + 2][1]);
            uint32_t ao1 = pack_h2(s[4 * kp + 2][2], s[4 * kp + 2][3]);
            uint32_t ao2 = pack_h2(s[4 * kp + 3][0], s[4 * kp + 3][1]);
            uint32_t ao3 = pack_h2(s[4 * kp + 3][2], s[4 * kp + 3][3]);
#pragma unroll
            for (int nn = 0; nn < 8; nn++) {
                uint4 Vv = *(const uint4*)&Vt[(nn * 8 + g) * GS + kp * 16 + 4 * t];
                mma_h(o[nn], ae0, ae1, ae2, ae3, Vv.x, Vv.y);
                mma_h(o[nn], ao0, ao1, ao2, ao3, Vv.z, Vv.w);
            }
        }
    }

    // finalize + store f32 natural [B,L,C] (R4 epilogue; cvt_perm rounds later)
    const int b_ = bh >> 4;
    const int h  = bh & (HEADS - 1);
    const float inv0 = 1.f / lrow0;
    const float inv1 = 1.f / lrow1;
    const int qrow = q0 + qr0;
    const size_t base0 = ((size_t)b_ * L_SEQ + qrow + g)     * CDIM + h * HD;
    const size_t base1 = ((size_t)b_ * L_SEQ + qrow + g + 8) * CDIM + h * HD;
#pragma unroll
    for (int nn = 0; nn < 8; nn++) {
        *(float2*)&att[base0 + nn * 8 + 2 * t] = make_float2(o[nn][0] * inv0, o[nn][1] * inv0);
        *(float2*)&att[base1 + nn * 8 + 2 * t] = make_float2(o[nn][2] * inv1, o[nn][3] * inv1);
    }
}

// ---------------------------------------------------------------------------
// Host launch
// ---------------------------------------------------------------------------
extern "C" void kernel_launch(void* const* d_in, const int* in_sizes, int n_in,
                              void* d_out, int out_size)
{
    const float* x       = (const float*)d_in[0];
    const float* w_qkv   = (const float*)d_in[1];
    const float* w_out   = (const float*)d_in[2];
    const float* q_scale = (const float*)d_in[3];
    const float* q_bias  = (const float*)d_in[4];
    const float* k_scale = (const float*)d_in[5];
    const float* k_bias  = (const float*)d_in[6];
    float* out = (float*)d_out;

    void *p_qkv, *p_q, *p_k, *p_v, *p_att, *p_xh, *p_wh, *p_worh, *p_atth;
    cudaGetSymbolAddress(&p_qkv, g_qkv);
    cudaGetSymbolAddress(&p_q, g_q);
    cudaGetSymbolAddress(&p_k, g_k);
    cudaGetSymbolAddress(&p_v, g_v);
    cudaGetSymbolAddress(&p_att, g_att);
    cudaGetSymbolAddress(&p_xh, g_xh);
    cudaGetSymbolAddress(&p_wh, g_wh);
    cudaGetSymbolAddress(&p_worh, g_worh);
    cudaGetSymbolAddress(&p_atth, g_atth);

    // 0) prep: x -> half perm16; weights -> transposed half perm16
    cvt_perm_kernel<<<(MTOT * 256 + 255) / 256, 256>>>(x, (uint32_t*)p_xh, MTOT * 256);
    transpose_cvt_perm_kernel<<<dim3(THREEC / 32, CDIM / 32), 256>>>(
        w_qkv, (uint32_t*)p_wh, CDIM, THREEC);
    transpose_cvt_perm_kernel<<<dim3(CDIM / 32, CDIM / 32), 256>>>(
        w_out, (uint32_t*)p_worh, CDIM, CDIM);

    // 1) QKV projection (fp16 tensor cores)
    cudaFuncSetAttribute(gemm_h_kernel, cudaFuncAttributeMaxDynamicSharedMemorySize,
                         GEMM_SMEM_BYTES);
    gemm_h_kernel<<<dim3(THREEC / 128, MTOT / 128), 256, GEMM_SMEM_BYTES>>>(
        (const uint32_t*)p_xh, (const uint32_t*)p_wh, (float*)p_qkv, MTOT, THREEC);

    // 2) QK LayerNorm + head split (tf32-rounded f32)
    ln_split_kernel<<<(MTOT * HEADS) / 8, 256>>>(
        (const float*)p_qkv, q_scale, q_bias, k_scale, k_bias,
        (float*)p_q, (float*)p_k, (float*)p_v);

    // 3) Flash attention (fp16 tensor cores) -> f32 natural layout
    cudaFuncSetAttribute(attn_h2_kernel, cudaFuncAttributeMaxDynamicSharedMemorySize,
                         ATTN_SMEM_BYTES);
    attn_h2_kernel<<<dim3(L_SEQ / 128, BATCH * HEADS), 256, ATTN_SMEM_BYTES>>>(
        (const float*)p_q, (const float*)p_k, (const float*)p_v, (float*)p_att);

    // 3b) convert attention output to half perm16
    cvt_perm_kernel<<<(MTOT * 256 + 255) / 256, 256>>>(
        (const float*)p_att, (uint32_t*)p_atth, MTOT * 256);

    // 4) Output projection (fp16 tensor cores)
    gemm_h_kernel<<<dim3(CDIM / 128, MTOT / 128), 256, GEMM_SMEM_BYTES>>>(
        (const uint32_t*)p_atth, (const uint32_t*)p_worh, out, MTOT, CDIM);
}

// round 12
// speedup vs baseline: 1.9611x; 1.0614x over previous
#include <cuda_runtime.h>
#include <cuda_fp16.h>
#include <cstdint>

// Problem constants
#define BATCH 2
#define L_SEQ 2048
#define CDIM  1024
#define HEADS 16
#define HD    64
#define MTOT  4096
#define THREEC 3072
#define INV4  0.3535533905932738f   // 64^-0.25

// ---------------------------------------------------------------------------
// Scratch (device globals; no allocation allowed)
// NOTE: q/k in [B,H,L,D] half layout need B*H*L*32 u32 = MTOT*512 u32
// (R8/R11 had these 16x too small -> OOB -> the correctness failures).
// ---------------------------------------------------------------------------
__device__ __align__(16) float    g_qkv [(size_t)MTOT * THREEC];  // f32 QKV out
__device__ __align__(16) uint32_t g_qh  [(size_t)MTOT * 512];     // q half perm16 [B,H,L]
__device__ __align__(16) uint32_t g_kh  [(size_t)MTOT * 512];     // k half perm16 [B,H,L]
__device__ __align__(16) float    g_v   [(size_t)MTOT * CDIM];    // v f32 [B,H,L,D]
__device__ __align__(16) float    g_att [(size_t)MTOT * CDIM];    // attn out f32 [B,L,C]
__device__ __align__(16) uint32_t g_xh  [(size_t)MTOT * 512];     // x half perm16
__device__ __align__(16) uint32_t g_wh  [(size_t)THREEC * 512];   // w_qkv^T half perm16
__device__ __align__(16) uint32_t g_worh[(size_t)CDIM * 512];     // w_out^T half perm16
__device__ __align__(16) uint32_t g_atth[(size_t)MTOT * 512];     // attn out half perm16

// ---------------------------------------------------------------------------
// Helpers
// ---------------------------------------------------------------------------
__device__ __forceinline__ int p16(int c) { return ((c & 3) << 2) | (c >> 2); }

__device__ __forceinline__ uint32_t pack_h2(float a, float b) {
    __half2 h = __floats2half2_rn(a, b);     // low = a, high = b
    return *reinterpret_cast<uint32_t*>(&h);
}

__device__ __forceinline__ uint32_t f2tf32(float f) {
    uint32_t r;
    asm("cvt.rna.tf32.f32 %0, %1;" : "=r"(r) : "f"(f));
    return r;
}

__device__ __forceinline__ void mma_h(float* d,
                                      uint32_t a0, uint32_t a1, uint32_t a2, uint32_t a3,
                                      uint32_t b0, uint32_t b1) {
    asm volatile(
        "mma.sync.aligned.m16n8k16.row.col.f32.f16.f16.f32 "
        "{%0,%1,%2,%3}, {%4,%5,%6,%7}, {%8,%9}, {%0,%1,%2,%3};\n"
        : "+f"(d[0]), "+f"(d[1]), "+f"(d[2]), "+f"(d[3])
        : "r"(a0), "r"(a1), "r"(a2), "r"(a3), "r"(b0), "r"(b1));
}

// ---------------------------------------------------------------------------
// Prep: f32 [R][1024] -> half u32 [R][512] with perm16 along K (validated)
// ---------------------------------------------------------------------------
__global__ __launch_bounds__(256) void cvt_perm_kernel(
    const float* __restrict__ src, uint32_t* __restrict__ dst, int n_f4)
{
    int i = blockIdx.x * blockDim.x + threadIdx.x;
    if (i >= n_f4) return;
    float4 v = ((const float4*)src)[i];
    int row = i >> 8;
    int f4  = i & 255;
    int k2a = 2 * f4, k2b = 2 * f4 + 1;
    int base = row * 512;
    dst[base + (k2a & ~15) + p16(k2a & 15)] = pack_h2(v.x, v.y);
    dst[base + (k2b & ~15) + p16(k2b & 15)] = pack_h2(v.z, v.w);
}

// f32 [K][C] -> half u32 [C][K/2] (transposed) with perm16 along K (validated)
__global__ __launch_bounds__(256) void transpose_cvt_perm_kernel(
    const float* __restrict__ src, uint32_t* __restrict__ dst, int K, int C)
{
    __shared__ float tile[32][33];
    const int c0 = blockIdx.x * 32, k0 = blockIdx.y * 32;
    const int tx = threadIdx.x & 31;
    const int ty = threadIdx.x >> 5;
#pragma unroll
    for (int j = 0; j < 4; j++)
        tile[ty + j * 8][tx] = src[(size_t)(k0 + ty + j * 8) * C + c0 + tx];
    __syncthreads();
#pragma unroll
    for (int j = 0; j < 2; j++) {
        int k2l = ty + 8 * j;
        uint32_t h = pack_h2(tile[2 * k2l][tx], tile[2 * k2l + 1][tx]);
        dst[(size_t)(c0 + tx) * (K / 2) + (k0 >> 1) + p16(k2l)] = h;
    }
}

// ---------------------------------------------------------------------------
// fp16 GEMM: C[M,N](f32) = A[M,K] * Bt[N,K]^T, perm16, K=1024.
// k-chunk 64 u32 (128 halves), smem row stride 80 (80%32==16, same residue
// as validated stride 48 -> unchanged bank behavior).
// smem: 2 x 128 x 80 x 4 = 81,920 B.
// ---------------------------------------------------------------------------
#define GSG 80
#define GEMM_SMEM_BYTES (2 * 128 * GSG * 4)

__global__ __launch_bounds__(256, 2) void gemm_h_kernel(
    const uint32_t* __restrict__ A, const uint32_t* __restrict__ Bt,
    float* __restrict__ C, int M, int N)
{
    extern __shared__ uint32_t us[];
    uint32_t* As = us;               // [128][80]
    uint32_t* Bs = us + 128 * GSG;   // [128][80]

    const int tid  = threadIdx.x;
    const int w    = tid >> 5;
    const int lane = tid & 31;
    const int g = lane >> 2;
    const int t = lane & 3;
    const int m0 = blockIdx.y * 128;
    const int n0 = blockIdx.x * 128;
    const int wr0 = w * 16;
    const int K2 = 512;

    float acc[16][4];
#pragma unroll
    for (int nn = 0; nn < 16; nn++)
#pragma unroll
        for (int v = 0; v < 4; v++) acc[nn][v] = 0.f;

    for (int k0 = 0; k0 < K2; k0 += 64) {
        __syncthreads();
#pragma unroll
        for (int i = 0; i < 8; i++) {
            int id = i * 256 + tid;
            int rr = id >> 4;
            int c4 = (id & 15) * 4;
            *(uint4*)&As[rr * GSG + c4] = *(const uint4*)&A[(size_t)(m0 + rr) * K2 + k0 + c4];
            *(uint4*)&Bs[rr * GSG + c4] = *(const uint4*)&Bt[(size_t)(n0 + rr) * K2 + k0 + c4];
        }
        __syncthreads();

#pragma unroll
        for (int kp = 0; kp < 4; kp++) {
            uint4 Ag  = *(const uint4*)&As[(wr0 + g)     * GSG + kp * 16 + 4 * t];
            uint4 Ag8 = *(const uint4*)&As[(wr0 + g + 8) * GSG + kp * 16 + 4 * t];
#pragma unroll
            for (int nn = 0; nn < 16; nn++) {
                uint4 Bv = *(const uint4*)&Bs[(nn * 8 + g) * GSG + kp * 16 + 4 * t];
                mma_h(acc[nn], Ag.x, Ag8.x, Ag.y, Ag8.y, Bv.x, Bv.y);
                mma_h(acc[nn], Ag.z, Ag8.z, Ag.w, Ag8.w, Bv.z, Bv.w);
            }
        }
    }

    const int row0 = m0 + wr0 + g;
    const int row1 = row0 + 8;
#pragma unroll
    for (int nn = 0; nn < 16; nn++) {
        const int col = n0 + nn * 8 + 2 * t;
        *(float2*)&C[(size_t)row0 * N + col] = make_float2(acc[nn][0], acc[nn][1]);
        *(float2*)&C[(size_t)row1 * N + col] = make_float2(acc[nn][2], acc[nn][3]);
    }
}

// ---------------------------------------------------------------------------
// LayerNorm(q,k)*D^-0.25 + split. q/k -> half perm16 u32[32]/token (math in
// f32; values well inside fp16 range). v -> f32 tf32-rounded.
// Lane l owns d = 2l, 2l+1 (d2 index = l).
// ---------------------------------------------------------------------------
__global__ __launch_bounds__(256) void ln_split_h_kernel(
    const float* __restrict__ qkv,
    const float* __restrict__ q_scale, const float* __restrict__ q_bias,
    const float* __restrict__ k_scale, const float* __restrict__ k_bias,
    uint32_t* __restrict__ q_h, uint32_t* __restrict__ k_h, float* __restrict__ v_t)
{
    const int wid  = (blockIdx.x * blockDim.x + threadIdx.x) >> 5;
    const int lane = threadIdx.x & 31;
    const int h = wid & (HEADS - 1);
    const int m = wid >> 4;
    const int b = m >> 11;
    const int l = m & (L_SEQ - 1);

    const float* row = qkv + (size_t)m * THREEC;
    const size_t tok = ((size_t)(b * HEADS + h)) * L_SEQ + l;
    const int d0 = 2 * lane, d1 = 2 * lane + 1;
    const int ppos = (lane & 16) | p16(lane & 15);

    {
        float x0 = row[h * HD + d0];
        float x1 = row[h * HD + d1];
        float s = x0 + x1;
#pragma unroll
        for (int o = 16; o > 0; o >>= 1) s += __shfl_xor_sync(0xffffffffu, s, o);
        float mu = s * (1.f / HD);
        float e0 = x0 - mu, e1 = x1 - mu;
        float vs = e0 * e0 + e1 * e1;
#pragma unroll
        for (int o = 16; o > 0; o >>= 1) vs += __shfl_xor_sync(0xffffffffu, vs, o);
        float rstd = rsqrtf(vs * (1.f / HD) + 1e-6f);
        float y0 = (e0 * rstd * q_scale[d0] + q_bias[d0]) * INV4;
        float y1 = (e1 * rstd * q_scale[d1] + q_bias[d1]) * INV4;
        q_h[tok * 32 + ppos] = pack_h2(y0, y1);
    }
    {
        float x0 = row[CDIM + h * HD + d0];
        float x1 = row[CDIM + h * HD + d1];
        float s = x0 + x1;
#pragma unroll
        for (int o = 16; o > 0; o >>= 1) s += __shfl_xor_sync(0xffffffffu, s, o);
        float mu = s * (1.f / HD);
        float e0 = x0 - mu, e1 = x1 - mu;
        float vs = e0 * e0 + e1 * e1;
#pragma unroll
        for (int o = 16; o > 0; o >>= 1) vs += __shfl_xor_sync(0xffffffffu, vs, o);
        float rstd = rsqrtf(vs * (1.f / HD) + 1e-6f);
        float y0 = (e0 * rstd * k_scale[d0] + k_bias[d0]) * INV4;
        float y1 = (e1 * rstd * k_scale[d1] + k_bias[d1]) * INV4;
        k_h[tok * 32 + ppos] = pack_h2(y0, y1);
    }
    v_t[tok * HD + lane]      = __uint_as_float(f2tf32(row[2 * CDIM + h * HD + lane]));
    v_t[tok * HD + lane + 32] = __uint_as_float(f2tf32(row[2 * CDIM + h * HD + lane + 32]));
}

// ---------------------------------------------------------------------------
// fp16 flash attention. Q/K pre-packed half perm16 (uint4 copies); V f32 in,
// transposed+packed in-kernel via validated shuffle path. f32 out.
// ---------------------------------------------------------------------------
#define GS 48
#define ATTN_SMEM_BYTES (256 * GS * 4)

__global__ __launch_bounds__(256, 2) void attn_h2_kernel(
    const uint32_t* __restrict__ q_h, const uint32_t* __restrict__ k_h,
    const float* __restrict__ v_t, float* __restrict__ att)
{
    extern __shared__ uint32_t us[];
    uint32_t* Qh = us;                    // [128][GS]
    uint32_t* Kh = us + 128 * GS;         // [64][GS]
    uint32_t* Vt = us + 192 * GS;         // [64][GS]

    const int tid  = threadIdx.x;
    const int w    = tid >> 5;
    const int lane = tid & 31;
    const int g = lane >> 2;
    const int t = lane & 3;
    const int bh = blockIdx.y;
    const int q0 = blockIdx.x * 128;
    const int qr0 = w * 16;

    const uint32_t* Qp = q_h + (size_t)bh * L_SEQ * 32;
    const uint32_t* Kp = k_h + (size_t)bh * L_SEQ * 32;
    const float*    Vp = v_t + (size_t)bh * L_SEQ * HD;

    // Q tile once: plain uint4 copies (layout already perm16)
#pragma unroll
    for (int i = 0; i < 4; i++) {
        int id = i * 256 + tid;
        int rr = id >> 3;
        int c4 = (id & 7) * 4;
        *(uint4*)&Qh[rr * GS + c4] = *(const uint4*)&Qp[(size_t)(q0 + rr) * 32 + c4];
    }

    float o[8][4];
#pragma unroll
    for (int nn = 0; nn < 8; nn++)
#pragma unroll
        for (int v = 0; v < 4; v++) o[nn][v] = 0.f;
    float mrow0 = -1e30f, mrow1 = -1e30f;
    float lrow0 = 0.f,    lrow1 = 0.f;

    for (int kt = 0; kt < L_SEQ; kt += 64) {
        __syncthreads();
        // K tile: plain uint4 copies
#pragma unroll
        for (int i = 0; i < 2; i++) {
            int id = i * 256 + tid;
            int rr = id >> 3;
            int c4 = (id & 7) * 4;
            *(uint4*)&Kh[rr * GS + c4] = *(const uint4*)&Kp[(size_t)(kt + rr) * 32 + c4];
        }
        // V tile transposed + key-pair packed: Vt[d][perm16(key2)] (R10-validated)
#pragma unroll
        for (int i = 0; i < 4; i++) {
            int idx = tid + i * 256;
            int key = idx & 63;
            int dg  = (idx >> 6) << 2;
            float4 mv = *(const float4*)&Vp[(size_t)(kt + key) * HD + dg];
            float4 pr;
            pr.x = __shfl_xor_sync(0xffffffffu, mv.x, 1);
            pr.y = __shfl_xor_sync(0xffffffffu, mv.y, 1);
            pr.z = __shfl_xor_sync(0xffffffffu, mv.z, 1);
            pr.w = __shfl_xor_sync(0xffffffffu, mv.w, 1);
            int key2 = key >> 1;
            int pos = (key2 & 16) | p16(key2 & 15);
            if (!(key & 1)) {
                Vt[(dg + 0) * GS + pos] = pack_h2(mv.x, pr.x);
                Vt[(dg + 1) * GS + pos] = pack_h2(mv.y, pr.y);
            } else {
                Vt[(dg + 2) * GS + pos] = pack_h2(pr.z, mv.z);
                Vt[(dg + 3) * GS + pos] = pack_h2(pr.w, mv.w);
            }
        }
        __syncthreads();

        // S = Q K^T (fp16)
        float s[8][4];
#pragma unroll
        for (int nn = 0; nn < 8; nn++)
#pragma unroll
            for (int v = 0; v < 4; v++) s[nn][v] = 0.f;

#pragma unroll
        for (int kp = 0; kp < 2; kp++) {
            uint4 Qg  = *(const uint4*)&Qh[(qr0 + g)     * GS + kp * 16 + 4 * t];
            uint4 Qg8 = *(const uint4*)&Qh[(qr0 + g + 8) * GS + kp * 16 + 4 * t];
#pragma unroll
            for (int nn = 0; nn < 8; nn++) {
                uint4 Kv = *(const uint4*)&Kh[(nn * 8 + g) * GS + kp * 16 + 4 * t];
                mma_h(s[nn], Qg.x, Qg8.x, Qg.y, Qg8.y, Kv.x, Kv.y);
                mma_h(s[nn], Qg.z, Qg8.z, Qg.w, Qg8.w, Kv.z, Kv.w);
            }
        }

        // online softmax (rows g, g+8; quad reductions)
        float mx0 = -1e30f, mx1 = -1e30f;
#pragma unroll
        for (int nn = 0; nn < 8; nn++) {
            mx0 = fmaxf(mx0, fmaxf(s[nn][0], s[nn][1]));
            mx1 = fmaxf(mx1, fmaxf(s[nn][2], s[nn][3]));
        }
        mx0 = fmaxf(mx0, __shfl_xor_sync(0xffffffffu, mx0, 1));
        mx0 = fmaxf(mx0, __shfl_xor_sync(0xffffffffu, mx0, 2));
        mx1 = fmaxf(mx1, __shfl_xor_sync(0xffffffffu, mx1, 1));
        mx1 = fmaxf(mx1, __shfl_xor_sync(0xffffffffu, mx1, 2));

        float mn0 = fmaxf(mrow0, mx0);
        float mn1 = fmaxf(mrow1, mx1);
        float alpha0 = __expf(mrow0 - mn0);
        float alpha1 = __expf(mrow1 - mn1);
        mrow0 = mn0; mrow1 = mn1;

        float rs0 = 0.f, rs1 = 0.f;
#pragma unroll
        for (int nn = 0; nn < 8; nn++) {
            s[nn][0] = __expf(s[nn][0] - mn0);
            s[nn][1] = __expf(s[nn][1] - mn0);
            s[nn][2] = __expf(s[nn][2] - mn1);
            s[nn][3] = __expf(s[nn][3] - mn1);
            rs0 += s[nn][0] + s[nn][1];
            rs1 += s[nn][2] + s[nn][3];
        }
        rs0 += __shfl_xor_sync(0xffffffffu, rs0, 1);
        rs0 += __shfl_xor_sync(0xffffffffu, rs0, 2);
        rs1 += __shfl_xor_sync(0xffffffffu, rs1, 1);
        rs1 += __shfl_xor_sync(0xffffffffu, rs1, 2);
        lrow0 = lrow0 * alpha0 + rs0;
        lrow1 = lrow1 * alpha1 + rs1;

#pragma unroll
        for (int nn = 0; nn < 8; nn++) {
            o[nn][0] *= alpha0; o[nn][1] *= alpha0;
            o[nn][2] *= alpha1; o[nn][3] *= alpha1;
        }

        // O += P V : register-only P repack (R10-validated ordering)
#pragma unroll
        for (int kp = 0; kp < 2; kp++) {
            uint32_t ae0 = pack_h2(s[4 * kp + 0][0], s[4 * kp + 0][1]);
            uint32_t ae1 = pack_h2(s[4 * kp + 0][2], s[4 * kp + 0][3]);
            uint32_t ae2 = pack_h2(s[4 * kp + 1][0], s[4 * kp + 1][1]);
            uint32_t ae3 = pack_h2(s[4 * kp + 1][2], s[4 * kp + 1][3]);
            uint32_t ao0 = pack_h2(s[4 * kp + 2][0], s[4 * kp + 2][1]);
            uint32_t ao1 = pack_h2(s[4 * kp + 2][2], s[4 * kp + 2][3]);
            uint32_t ao2 = pack_h2(s[4 * kp + 3][0], s[4 * kp + 3][1]);
            uint32_t ao3 = pack_h2(s[4 * kp + 3][2], s[4 * kp + 3][3]);
#pragma unroll
            for (int nn = 0; nn < 8; nn++) {
                uint4 Vv = *(const uint4*)&Vt[(nn * 8 + g) * GS + kp * 16 + 4 * t];
                mma_h(o[nn], ae0, ae1, ae2, ae3, Vv.x, Vv.y);
                mma_h(o[nn], ao0, ao1, ao2, ao3, Vv.z, Vv.w);
            }
        }
    }

    // finalize + store f32 natural [B,L,C]
    const int b_ = bh >> 4;
    const int h  = bh & (HEADS - 1);
    const float inv0 = 1.f / lrow0;
    const float inv1 = 1.f / lrow1;
    const int qrow = q0 + qr0;
    const size_t base0 = ((size_t)b_ * L_SEQ + qrow + g)     * CDIM + h * HD;
    const size_t base1 = ((size_t)b_ * L_SEQ + qrow + g + 8) * CDIM + h * HD;
#pragma unroll
    for (int nn = 0; nn < 8; nn++) {
        *(float2*)&att[base0 + nn * 8 + 2 * t] = make_float2(o[nn][0] * inv0, o[nn][1] * inv0);
        *(float2*)&att[base1 + nn * 8 + 2 * t] = make_float2(o[nn][2] * inv1, o[nn][3] * inv1);
    }
}

// ---------------------------------------------------------------------------
// Host launch
// ---------------------------------------------------------------------------
extern "C" void kernel_launch(void* const* d_in, const int* in_sizes, int n_in,
                              void* d_out, int out_size)
{
    const float* x       = (const float*)d_in[0];
    const float* w_qkv   = (const float*)d_in[1];
    const float* w_out   = (const float*)d_in[2];
    const float* q_scale = (const float*)d_in[3];
    const float* q_bias  = (const float*)d_in[4];
    const float* k_scale = (const float*)d_in[5];
    const float* k_bias  = (const float*)d_in[6];
    float* out = (float*)d_out;

    void *p_qkv, *p_qh, *p_kh, *p_v, *p_att, *p_xh, *p_wh, *p_worh, *p_atth;
    cudaGetSymbolAddress(&p_qkv, g_qkv);
    cudaGetSymbolAddress(&p_qh, g_qh);
    cudaGetSymbolAddress(&p_kh, g_kh);
    cudaGetSymbolAddress(&p_v, g_v);
    cudaGetSymbolAddress(&p_att, g_att);
    cudaGetSymbolAddress(&p_xh, g_xh);
    cudaGetSymbolAddress(&p_wh, g_wh);
    cudaGetSymbolAddress(&p_worh, g_worh);
    cudaGetSymbolAddress(&p_atth, g_atth);

    // 0) prep
    cvt_perm_kernel<<<(MTOT * 256 + 255) / 256, 256>>>(x, (uint32_t*)p_xh, MTOT * 256);
    transpose_cvt_perm_kernel<<<dim3(THREEC / 32, CDIM / 32), 256>>>(
        w_qkv, (uint32_t*)p_wh, CDIM, THREEC);
    transpose_cvt_perm_kernel<<<dim3(CDIM / 32, CDIM / 32), 256>>>(
        w_out, (uint32_t*)p_worh, CDIM, CDIM);

    // 1) QKV projection
    cudaFuncSetAttribute(gemm_h_kernel, cudaFuncAttributeMaxDynamicSharedMemorySize,
                         GEMM_SMEM_BYTES);
    gemm_h_kernel<<<dim3(THREEC / 128, MTOT / 128), 256, GEMM_SMEM_BYTES>>>(
        (const uint32_t*)p_xh, (const uint32_t*)p_wh, (float*)p_qkv, MTOT, THREEC);

    // 2) QK LayerNorm + split (q/k half perm16, v f32)
    ln_split_h_kernel<<<(MTOT * HEADS) / 8, 256>>>(
        (const float*)p_qkv, q_scale, q_bias, k_scale, k_bias,
        (uint32_t*)p_qh, (uint32_t*)p_kh, (float*)p_v);

    // 3) Flash attention
    cudaFuncSetAttribute(attn_h2_kernel, cudaFuncAttributeMaxDynamicSharedMemorySize,
                         ATTN_SMEM_BYTES);
    attn_h2_kernel<<<dim3(L_SEQ / 128, BATCH * HEADS), 256, ATTN_SMEM_BYTES>>>(
        (const uint32_t*)p_qh, (const uint32_t*)p_kh, (const float*)p_v, (float*)p_att);

    // 3b) attention output -> half perm16
    cvt_perm_kernel<<<(MTOT * 256 + 255) / 256, 256>>>(
        (const float*)p_att, (uint32_t*)p_atth, MTOT * 256);

    // 4) Output projection
    gemm_h_kernel<<<dim3(CDIM / 128, MTOT / 128), 256, GEMM_SMEM_BYTES>>>(
        (const uint32_t*)p_atth, (const uint32_t*)p_worh, out, MTOT, CDIM);
}

// round 13
// speedup vs baseline: 1.9679x; 1.0035x over previous
#include <cuda_runtime.h>
#include <cuda_fp16.h>
#include <cstdint>

// Problem constants
#define BATCH 2
#define L_SEQ 2048
#define CDIM  1024
#define HEADS 16
#define HD    64
#define MTOT  4096
#define THREEC 3072
#define INV4  0.3535533905932738f   // 64^-0.25

// ---------------------------------------------------------------------------
// Scratch (device globals; no allocation allowed)
// ---------------------------------------------------------------------------
__device__ __align__(16) float    g_qkv [(size_t)MTOT * THREEC];  // f32 QKV out
__device__ __align__(16) uint32_t g_qh  [(size_t)MTOT * 512];     // q half perm16 [B,H,L]
__device__ __align__(16) uint32_t g_kh  [(size_t)MTOT * 512];     // k half perm16 [B,H,L]
__device__ __align__(16) float    g_v   [(size_t)MTOT * CDIM];    // v f32 [B,H,L,D]
__device__ __align__(16) uint32_t g_xh  [(size_t)MTOT * 512];     // x half perm16
__device__ __align__(16) uint32_t g_wh  [(size_t)THREEC * 512];   // w_qkv^T half perm16
__device__ __align__(16) uint32_t g_worh[(size_t)CDIM * 512];     // w_out^T half perm16
__device__ __align__(16) uint32_t g_atth[(size_t)MTOT * 512];     // attn out half perm16

// ---------------------------------------------------------------------------
// Helpers
// ---------------------------------------------------------------------------
__device__ __forceinline__ int p16(int c) { return ((c & 3) << 2) | (c >> 2); }

__device__ __forceinline__ uint32_t pack_h2(float a, float b) {
    __half2 h = __floats2half2_rn(a, b);     // low = a, high = b
    return *reinterpret_cast<uint32_t*>(&h);
}

__device__ __forceinline__ uint32_t f2tf32(float f) {
    uint32_t r;
    asm("cvt.rna.tf32.f32 %0, %1;" : "=r"(r) : "f"(f));
    return r;
}

__device__ __forceinline__ void mma_h(float* d,
                                      uint32_t a0, uint32_t a1, uint32_t a2, uint32_t a3,
                                      uint32_t b0, uint32_t b1) {
    asm volatile(
        "mma.sync.aligned.m16n8k16.row.col.f32.f16.f16.f32 "
        "{%0,%1,%2,%3}, {%4,%5,%6,%7}, {%8,%9}, {%0,%1,%2,%3};\n"
        : "+f"(d[0]), "+f"(d[1]), "+f"(d[2]), "+f"(d[3])
        : "r"(a0), "r"(a1), "r"(a2), "r"(a3), "r"(b0), "r"(b1));
}

// ---------------------------------------------------------------------------
// Prep: f32 [R][1024] -> half u32 [R][512] with perm16 along K (validated)
// ---------------------------------------------------------------------------
__global__ __launch_bounds__(256) void cvt_perm_kernel(
    const float* __restrict__ src, uint32_t* __restrict__ dst, int n_f4)
{
    int i = blockIdx.x * blockDim.x + threadIdx.x;
    if (i >= n_f4) return;
    float4 v = ((const float4*)src)[i];
    int row = i >> 8;
    int f4  = i & 255;
    int k2a = 2 * f4, k2b = 2 * f4 + 1;
    int base = row * 512;
    dst[base + (k2a & ~15) + p16(k2a & 15)] = pack_h2(v.x, v.y);
    dst[base + (k2b & ~15) + p16(k2b & 15)] = pack_h2(v.z, v.w);
}

// f32 [K][C] -> half u32 [C][K/2] (transposed) with perm16 along K (validated)
__global__ __launch_bounds__(256) void transpose_cvt_perm_kernel(
    const float* __restrict__ src, uint32_t* __restrict__ dst, int K, int C)
{
    __shared__ float tile[32][33];
    const int c0 = blockIdx.x * 32, k0 = blockIdx.y * 32;
    const int tx = threadIdx.x & 31;
    const int ty = threadIdx.x >> 5;
#pragma unroll
    for (int j = 0; j < 4; j++)
        tile[ty + j * 8][tx] = src[(size_t)(k0 + ty + j * 8) * C + c0 + tx];
    __syncthreads();
#pragma unroll
    for (int j = 0; j < 2; j++) {
        int k2l = ty + 8 * j;
        uint32_t h = pack_h2(tile[2 * k2l][tx], tile[2 * k2l + 1][tx]);
        dst[(size_t)(c0 + tx) * (K / 2) + (k0 >> 1) + p16(k2l)] = h;
    }
}

// ---------------------------------------------------------------------------
// fp16 GEMM: C[M,N](f32) = A[M,K] * Bt[N,K]^T, perm16, K=1024.
// k-chunk 64 u32, stride 80. 8 warps in 4m x 2n grid, each 32 rows x 64 cols
// (12 LDS.128 per 32 mma vs 18 for the 16x128 shape; 2 independent m-groups).
// ---------------------------------------------------------------------------
#define GSG 80
#define GEMM_SMEM_BYTES (2 * 128 * GSG * 4)

__global__ __launch_bounds__(256, 2) void gemm_h_kernel(
    const uint32_t* __restrict__ A, const uint32_t* __restrict__ Bt,
    float* __restrict__ C, int M, int N)
{
    extern __shared__ uint32_t us[];
    uint32_t* As = us;               // [128][80]
    uint32_t* Bs = us + 128 * GSG;   // [128][80]

    const int tid  = threadIdx.x;
    const int w    = tid >> 5;
    const int lane = tid & 31;
    const int g = lane >> 2;
    const int t = lane & 3;
    const int m0 = blockIdx.y * 128;
    const int n0 = blockIdx.x * 128;
    const int wm = (w & 3) * 32;     // warp m base (32 rows)
    const int wn = (w >> 2) * 64;    // warp n base (64 cols)
    const int K2 = 512;

    float acc[2][8][4];
#pragma unroll
    for (int mg = 0; mg < 2; mg++)
#pragma unroll
        for (int nn = 0; nn < 8; nn++)
#pragma unroll
            for (int v = 0; v < 4; v++) acc[mg][nn][v] = 0.f;

    for (int k0 = 0; k0 < K2; k0 += 64) {
        __syncthreads();
#pragma unroll
        for (int i = 0; i < 8; i++) {
            int id = i * 256 + tid;
            int rr = id >> 4;
            int c4 = (id & 15) * 4;
            *(uint4*)&As[rr * GSG + c4] = *(const uint4*)&A[(size_t)(m0 + rr) * K2 + k0 + c4];
            *(uint4*)&Bs[rr * GSG + c4] = *(const uint4*)&Bt[(size_t)(n0 + rr) * K2 + k0 + c4];
        }
        __syncthreads();

#pragma unroll
        for (int kp = 0; kp < 4; kp++) {
            uint4 Ag[2][2];
#pragma unroll
            for (int mg = 0; mg < 2; mg++) {
                Ag[mg][0] = *(const uint4*)&As[(wm + mg * 16 + g)     * GSG + kp * 16 + 4 * t];
                Ag[mg][1] = *(const uint4*)&As[(wm + mg * 16 + g + 8) * GSG + kp * 16 + 4 * t];
            }
#pragma unroll
            for (int nn = 0; nn < 8; nn++) {
                uint4 Bv = *(const uint4*)&Bs[(wn + nn * 8 + g) * GSG + kp * 16 + 4 * t];
#pragma unroll
                for (int mg = 0; mg < 2; mg++) {
                    mma_h(acc[mg][nn], Ag[mg][0].x, Ag[mg][1].x, Ag[mg][0].y, Ag[mg][1].y,
                          Bv.x, Bv.y);
                    mma_h(acc[mg][nn], Ag[mg][0].z, Ag[mg][1].z, Ag[mg][0].w, Ag[mg][1].w,
                          Bv.z, Bv.w);
                }
            }
        }
    }

#pragma unroll
    for (int mg = 0; mg < 2; mg++) {
        const int row0 = m0 + wm + mg * 16 + g;
        const int row1 = row0 + 8;
#pragma unroll
        for (int nn = 0; nn < 8; nn++) {
            const int col = n0 + wn + nn * 8 + 2 * t;
            *(float2*)&C[(size_t)row0 * N + col] = make_float2(acc[mg][nn][0], acc[mg][nn][1]);
            *(float2*)&C[(size_t)row1 * N + col] = make_float2(acc[mg][nn][2], acc[mg][nn][3]);
        }
    }
}

// ---------------------------------------------------------------------------
// LayerNorm(q,k)*D^-0.25 + split. q/k -> half perm16; v -> f32 (R12 verbatim)
// ---------------------------------------------------------------------------
__global__ __launch_bounds__(256) void ln_split_h_kernel(
    const float* __restrict__ qkv,
    const float* __restrict__ q_scale, const float* __restrict__ q_bias,
    const float* __restrict__ k_scale, const float* __restrict__ k_bias,
    uint32_t* __restrict__ q_h, uint32_t* __restrict__ k_h, float* __restrict__ v_t)
{
    const int wid  = (blockIdx.x * blockDim.x + threadIdx.x) >> 5;
    const int lane = threadIdx.x & 31;
    const int h = wid & (HEADS - 1);
    const int m = wid >> 4;
    const int b = m >> 11;
    const int l = m & (L_SEQ - 1);

    const float* row = qkv + (size_t)m * THREEC;
    const size_t tok = ((size_t)(b * HEADS + h)) * L_SEQ + l;
    const int d0 = 2 * lane, d1 = 2 * lane + 1;
    const int ppos = (lane & 16) | p16(lane & 15);

    {
        float x0 = row[h * HD + d0];
        float x1 = row[h * HD + d1];
        float s = x0 + x1;
#pragma unroll
        for (int o = 16; o > 0; o >>= 1) s += __shfl_xor_sync(0xffffffffu, s, o);
        float mu = s * (1.f / HD);
        float e0 = x0 - mu, e1 = x1 - mu;
        float vs = e0 * e0 + e1 * e1;
#pragma unroll
        for (int o = 16; o > 0; o >>= 1) vs += __shfl_xor_sync(0xffffffffu, vs, o);
        float rstd = rsqrtf(vs * (1.f / HD) + 1e-6f);
        float y0 = (e0 * rstd * q_scale[d0] + q_bias[d0]) * INV4;
        float y1 = (e1 * rstd * q_scale[d1] + q_bias[d1]) * INV4;
        q_h[tok * 32 + ppos] = pack_h2(y0, y1);
    }
    {
        float x0 = row[CDIM + h * HD + d0];
        float x1 = row[CDIM + h * HD + d1];
        float s = x0 + x1;
#pragma unroll
        for (int o = 16; o > 0; o >>= 1) s += __shfl_xor_sync(0xffffffffu, s, o);
        float mu = s * (1.f / HD);
        float e0 = x0 - mu, e1 = x1 - mu;
        float vs = e0 * e0 + e1 * e1;
#pragma unroll
        for (int o = 16; o > 0; o >>= 1) vs += __shfl_xor_sync(0xffffffffu, vs, o);
        float rstd = rsqrtf(vs * (1.f / HD) + 1e-6f);
        float y0 = (e0 * rstd * k_scale[d0] + k_bias[d0]) * INV4;
        float y1 = (e1 * rstd * k_scale[d1] + k_bias[d1]) * INV4;
        k_h[tok * 32 + ppos] = pack_h2(y0, y1);
    }
    v_t[tok * HD + lane]      = __uint_as_float(f2tf32(row[2 * CDIM + h * HD + lane]));
    v_t[tok * HD + lane + 32] = __uint_as_float(f2tf32(row[2 * CDIM + h * HD + lane + 32]));
}

// ---------------------------------------------------------------------------
// fp16 flash attention (R12 body). Epilogue now writes half perm16 directly
// to g_atth (bit-identical values to the old f32-store + cvt_perm pass).
// ---------------------------------------------------------------------------
#define GS 48
#define ATTN_SMEM_BYTES (256 * GS * 4)

__global__ __launch_bounds__(256, 2) void attn_h2_kernel(
    const uint32_t* __restrict__ q_h, const uint32_t* __restrict__ k_h,
    const float* __restrict__ v_t, uint32_t* __restrict__ atth)
{
    extern __shared__ uint32_t us[];
    uint32_t* Qh = us;                    // [128][GS]
    uint32_t* Kh = us + 128 * GS;         // [64][GS]
    uint32_t* Vt = us + 192 * GS;         // [64][GS]

    const int tid  = threadIdx.x;
    const int w    = tid >> 5;
    const int lane = tid & 31;
    const int g = lane >> 2;
    const int t = lane & 3;
    const int bh = blockIdx.y;
    const int q0 = blockIdx.x * 128;
    const int qr0 = w * 16;

    const uint32_t* Qp = q_h + (size_t)bh * L_SEQ * 32;
    const uint32_t* Kp = k_h + (size_t)bh * L_SEQ * 32;
    const float*    Vp = v_t + (size_t)bh * L_SEQ * HD;

    // Q tile once: plain uint4 copies
#pragma unroll
    for (int i = 0; i < 4; i++) {
        int id = i * 256 + tid;
        int rr = id >> 3;
        int c4 = (id & 7) * 4;
        *(uint4*)&Qh[rr * GS + c4] = *(const uint4*)&Qp[(size_t)(q0 + rr) * 32 + c4];
    }

    float o[8][4];
#pragma unroll
    for (int nn = 0; nn < 8; nn++)
#pragma unroll
        for (int v = 0; v < 4; v++) o[nn][v] = 0.f;
    float mrow0 = -1e30f, mrow1 = -1e30f;
    float lrow0 = 0.f,    lrow1 = 0.f;

    for (int kt = 0; kt < L_SEQ; kt += 64) {
        __syncthreads();
        // K tile: plain uint4 copies
#pragma unroll
        for (int i = 0; i < 2; i++) {
            int id = i * 256 + tid;
            int rr = id >> 3;
            int c4 = (id & 7) * 4;
            *(uint4*)&Kh[rr * GS + c4] = *(const uint4*)&Kp[(size_t)(kt + rr) * 32 + c4];
        }
        // V tile transposed + key-pair packed (validated)
#pragma unroll
        for (int i = 0; i < 4; i++) {
            int idx = tid + i * 256;
            int key = idx & 63;
            int dg  = (idx >> 6) << 2;
            float4 mv = *(const float4*)&Vp[(size_t)(kt + key) * HD + dg];
            float4 pr;
            pr.x = __shfl_xor_sync(0xffffffffu, mv.x, 1);
            pr.y = __shfl_xor_sync(0xffffffffu, mv.y, 1);
            pr.z = __shfl_xor_sync(0xffffffffu, mv.z, 1);
            pr.w = __shfl_xor_sync(0xffffffffu, mv.w, 1);
            int key2 = key >> 1;
            int pos = (key2 & 16) | p16(key2 & 15);
            if (!(key & 1)) {
                Vt[(dg + 0) * GS + pos] = pack_h2(mv.x, pr.x);
                Vt[(dg + 1) * GS + pos] = pack_h2(mv.y, pr.y);
            } else {
                Vt[(dg + 2) * GS + pos] = pack_h2(pr.z, mv.z);
                Vt[(dg + 3) * GS + pos] = pack_h2(pr.w, mv.w);
            }
        }
        __syncthreads();

        // S = Q K^T (fp16)
        float s[8][4];
#pragma unroll
        for (int nn = 0; nn < 8; nn++)
#pragma unroll
            for (int v = 0; v < 4; v++) s[nn][v] = 0.f;

#pragma unroll
        for (int kp = 0; kp < 2; kp++) {
            uint4 Qg  = *(const uint4*)&Qh[(qr0 + g)     * GS + kp * 16 + 4 * t];
            uint4 Qg8 = *(const uint4*)&Qh[(qr0 + g + 8) * GS + kp * 16 + 4 * t];
#pragma unroll
            for (int nn = 0; nn < 8; nn++) {
                uint4 Kv = *(const uint4*)&Kh[(nn * 8 + g) * GS + kp * 16 + 4 * t];
                mma_h(s[nn], Qg.x, Qg8.x, Qg.y, Qg8.y, Kv.x, Kv.y);
                mma_h(s[nn], Qg.z, Qg8.z, Qg.w, Qg8.w, Kv.z, Kv.w);
            }
        }

        // online softmax (rows g, g+8; quad reductions)
        float mx0 = -1e30f, mx1 = -1e30f;
#pragma unroll
        for (int nn = 0; nn < 8; nn++) {
            mx0 = fmaxf(mx0, fmaxf(s[nn][0], s[nn][1]));
            mx1 = fmaxf(mx1, fmaxf(s[nn][2], s[nn][3]));
        }
        mx0 = fmaxf(mx0, __shfl_xor_sync(0xffffffffu, mx0, 1));
        mx0 = fmaxf(mx0, __shfl_xor_sync(0xffffffffu, mx0, 2));
        mx1 = fmaxf(mx1, __shfl_xor_sync(0xffffffffu, mx1, 1));
        mx1 = fmaxf(mx1, __shfl_xor_sync(0xffffffffu, mx1, 2));

        float mn0 = fmaxf(mrow0, mx0);
        float mn1 = fmaxf(mrow1, mx1);
        float alpha0 = __expf(mrow0 - mn0);
        float alpha1 = __expf(mrow1 - mn1);
        mrow0 = mn0; mrow1 = mn1;

        float rs0 = 0.f, rs1 = 0.f;
#pragma unroll
        for (int nn = 0; nn < 8; nn++) {
            s[nn][0] = __expf(s[nn][0] - mn0);
            s[nn][1] = __expf(s[nn][1] - mn0);
            s[nn][2] = __expf(s[nn][2] - mn1);
            s[nn][3] = __expf(s[nn][3] - mn1);
            rs0 += s[nn][0] + s[nn][1];
            rs1 += s[nn][2] + s[nn][3];
        }
        rs0 += __shfl_xor_sync(0xffffffffu, rs0, 1);
        rs0 += __shfl_xor_sync(0xffffffffu, rs0, 2);
        rs1 += __shfl_xor_sync(0xffffffffu, rs1, 1);
        rs1 += __shfl_xor_sync(0xffffffffu, rs1, 2);
        lrow0 = lrow0 * alpha0 + rs0;
        lrow1 = lrow1 * alpha1 + rs1;

#pragma unroll
        for (int nn = 0; nn < 8; nn++) {
            o[nn][0] *= alpha0; o[nn][1] *= alpha0;
            o[nn][2] *= alpha1; o[nn][3] *= alpha1;
        }

        // O += P V : register-only P repack (validated ordering)
#pragma unroll
        for (int kp = 0; kp < 2; kp++) {
            uint32_t ae0 = pack_h2(s[4 * kp + 0][0], s[4 * kp + 0][1]);
            uint32_t ae1 = pack_h2(s[4 * kp + 0][2], s[4 * kp + 0][3]);
            uint32_t ae2 = pack_h2(s[4 * kp + 1][0], s[4 * kp + 1][1]);
            uint32_t ae3 = pack_h2(s[4 * kp + 1][2], s[4 * kp + 1][3]);
            uint32_t ao0 = pack_h2(s[4 * kp + 2][0], s[4 * kp + 2][1]);
            uint32_t ao1 = pack_h2(s[4 * kp + 2][2], s[4 * kp + 2][3]);
            uint32_t ao2 = pack_h2(s[4 * kp + 3][0], s[4 * kp + 3][1]);
            uint32_t ao3 = pack_h2(s[4 * kp + 3][2], s[4 * kp + 3][3]);
#pragma unroll
            for (int nn = 0; nn < 8; nn++) {
                uint4 Vv = *(const uint4*)&Vt[(nn * 8 + g) * GS + kp * 16 + 4 * t];
                mma_h(o[nn], ae0, ae1, ae2, ae3, Vv.x, Vv.y);
                mma_h(o[nn], ao0, ao1, ao2, ao3, Vv.z, Vv.w);
            }
        }
    }

    // finalize + store half perm16 directly (identical values to cvt_perm path)
    const int b_ = bh >> 4;
    const int h  = bh & (HEADS - 1);
    const float inv0 = 1.f / lrow0;
    const float inv1 = 1.f / lrow1;
    const int tok0 = b_ * L_SEQ + q0 + qr0 + g;
    const int tok1 = tok0 + 8;
#pragma unroll
    for (int nn = 0; nn < 8; nn++) {
        int pos = h * 32 + ((nn >> 2) << 4) + 4 * t + (nn & 3);
        atth[(size_t)tok0 * 512 + pos] = pack_h2(o[nn][0] * inv0, o[nn][1] * inv0);
        atth[(size_t)tok1 * 512 + pos] = pack_h2(o[nn][2] * inv1, o[nn][3] * inv1);
    }
}

// ---------------------------------------------------------------------------
// Host launch
// ---------------------------------------------------------------------------
extern "C" void kernel_launch(void* const* d_in, const int* in_sizes, int n_in,
                              void* d_out, int out_size)
{
    const float* x       = (const float*)d_in[0];
    const float* w_qkv   = (const float*)d_in[1];
    const float* w_out   = (const float*)d_in[2];
    const float* q_scale = (const float*)d_in[3];
    const float* q_bias  = (const float*)d_in[4];
    const float* k_scale = (const float*)d_in[5];
    const float* k_bias  = (const float*)d_in[6];
    float* out = (float*)d_out;

    void *p_qkv, *p_qh, *p_kh, *p_v, *p_xh, *p_wh, *p_worh, *p_atth;
    cudaGetSymbolAddress(&p_qkv, g_qkv);
    cudaGetSymbolAddress(&p_qh, g_qh);
    cudaGetSymbolAddress(&p_kh, g_kh);
    cudaGetSymbolAddress(&p_v, g_v);
    cudaGetSymbolAddress(&p_xh, g_xh);
    cudaGetSymbolAddress(&p_wh, g_wh);
    cudaGetSymbolAddress(&p_worh, g_worh);
    cudaGetSymbolAddress(&p_atth, g_atth);

    // 0) prep
    cvt_perm_kernel<<<(MTOT * 256 + 255) / 256, 256>>>(x, (uint32_t*)p_xh, MTOT * 256);
    transpose_cvt_perm_kernel<<<dim3(THREEC / 32, CDIM / 32), 256>>>(
        w_qkv, (uint32_t*)p_wh, CDIM, THREEC);
    transpose_cvt_perm_kernel<<<dim3(CDIM / 32, CDIM / 32), 256>>>(
        w_out, (uint32_t*)p_worh, CDIM, CDIM);

    // 1) QKV projection
    cudaFuncSetAttribute(gemm_h_kernel, cudaFuncAttributeMaxDynamicSharedMemorySize,
                         GEMM_SMEM_BYTES);
    gemm_h_kernel<<<dim3(THREEC / 128, MTOT / 128), 256, GEMM_SMEM_BYTES>>>(
        (const uint32_t*)p_xh, (const uint32_t*)p_wh, (float*)p_qkv, MTOT, THREEC);

    // 2) QK LayerNorm + split (q/k half perm16, v f32)
    ln_split_h_kernel<<<(MTOT * HEADS) / 8, 256>>>(
        (const float*)p_qkv, q_scale, q_bias, k_scale, k_bias,
        (uint32_t*)p_qh, (uint32_t*)p_kh, (float*)p_v);

    // 3) Flash attention -> half perm16 directly
    cudaFuncSetAttribute(attn_h2_kernel, cudaFuncAttributeMaxDynamicSharedMemorySize,
                         ATTN_SMEM_BYTES);
    attn_h2_kernel<<<dim3(L_SEQ / 128, BATCH * HEADS), 256, ATTN_SMEM_BYTES>>>(
        (const uint32_t*)p_qh, (const uint32_t*)p_kh, (const float*)p_v,
        (uint32_t*)p_atth);

    // 4) Output projection
    gemm_h_kernel<<<dim3(CDIM / 128, MTOT / 128), 256, GEMM_SMEM_BYTES>>>(
        (const uint32_t*)p_atth, (const uint32_t*)p_worh, out, MTOT, CDIM);
}

// round 14
// speedup vs baseline: 2.0362x; 1.0347x over previous
#include <cuda_runtime.h>
#include <cuda_fp16.h>
#include <cstdint>

// Problem constants
#define BATCH 2
#define L_SEQ 2048
#define CDIM  1024
#define HEADS 16
#define HD    64
#define MTOT  4096
#define THREEC 3072
#define INV4  0.3535533905932738f   // 64^-0.25

// ---------------------------------------------------------------------------
// Scratch (device globals; no allocation allowed)
// ---------------------------------------------------------------------------
__device__ __align__(16) float    g_qkv [(size_t)MTOT * THREEC];  // f32 QKV out
__device__ __align__(16) uint32_t g_qh  [(size_t)MTOT * 512];     // q half perm16 [B,H,L]
__device__ __align__(16) uint32_t g_kh  [(size_t)MTOT * 512];     // k half perm16 [B,H,L]
__device__ __align__(16) float    g_v   [(size_t)MTOT * CDIM];    // v f32 [B,H,L,D]
__device__ __align__(16) uint32_t g_xh  [(size_t)MTOT * 512];     // x half perm16
__device__ __align__(16) uint32_t g_wh  [(size_t)THREEC * 512];   // w_qkv^T half perm16
__device__ __align__(16) uint32_t g_worh[(size_t)CDIM * 512];     // w_out^T half perm16
__device__ __align__(16) uint32_t g_atth[(size_t)MTOT * 512];     // attn out half perm16

// ---------------------------------------------------------------------------
// Helpers
// ---------------------------------------------------------------------------
__device__ __forceinline__ int p16(int c) { return ((c & 3) << 2) | (c >> 2); }

__device__ __forceinline__ uint32_t pack_h2(float a, float b) {
    __half2 h = __floats2half2_rn(a, b);     // low = a, high = b
    return *reinterpret_cast<uint32_t*>(&h);
}

__device__ __forceinline__ uint32_t f2tf32(float f) {
    uint32_t r;
    asm("cvt.rna.tf32.f32 %0, %1;" : "=r"(r) : "f"(f));
    return r;
}

__device__ __forceinline__ void mma_h(float* d,
                                      uint32_t a0, uint32_t a1, uint32_t a2, uint32_t a3,
                                      uint32_t b0, uint32_t b1) {
    asm volatile(
        "mma.sync.aligned.m16n8k16.row.col.f32.f16.f16.f32 "
        "{%0,%1,%2,%3}, {%4,%5,%6,%7}, {%8,%9}, {%0,%1,%2,%3};\n"
        : "+f"(d[0]), "+f"(d[1]), "+f"(d[2]), "+f"(d[3])
        : "r"(a0), "r"(a1), "r"(a2), "r"(a3), "r"(b0), "r"(b1));
}

__device__ __forceinline__ void cp16(void* smem, const void* gmem) {
    uint32_t s = (uint32_t)__cvta_generic_to_shared(smem);
    asm volatile("cp.async.ca.shared.global [%0], [%1], 16;" :: "r"(s), "l"(gmem));
}
__device__ __forceinline__ void cp_commit() { asm volatile("cp.async.commit_group;"); }
__device__ __forceinline__ void cp_wait0()  { asm volatile("cp.async.wait_group 0;"); }

// ---------------------------------------------------------------------------
// Prep: f32 [R][1024] -> half u32 [R][512] with perm16 along K (validated)
// ---------------------------------------------------------------------------
__global__ __launch_bounds__(256) void cvt_perm_kernel(
    const float* __restrict__ src, uint32_t* __restrict__ dst, int n_f4)
{
    int i = blockIdx.x * blockDim.x + threadIdx.x;
    if (i >= n_f4) return;
    float4 v = ((const float4*)src)[i];
    int row = i >> 8;
    int f4  = i & 255;
    int k2a = 2 * f4, k2b = 2 * f4 + 1;
    int base = row * 512;
    dst[base + (k2a & ~15) + p16(k2a & 15)] = pack_h2(v.x, v.y);
    dst[base + (k2b & ~15) + p16(k2b & 15)] = pack_h2(v.z, v.w);
}

// f32 [K][C] -> half u32 [C][K/2] (transposed) with perm16 along K (validated)
__global__ __launch_bounds__(256) void transpose_cvt_perm_kernel(
    const float* __restrict__ src, uint32_t* __restrict__ dst, int K, int C)
{
    __shared__ float tile[32][33];
    const int c0 = blockIdx.x * 32, k0 = blockIdx.y * 32;
    const int tx = threadIdx.x & 31;
    const int ty = threadIdx.x >> 5;
#pragma unroll
    for (int j = 0; j < 4; j++)
        tile[ty + j * 8][tx] = src[(size_t)(k0 + ty + j * 8) * C + c0 + tx];
    __syncthreads();
#pragma unroll
    for (int j = 0; j < 2; j++) {
        int k2l = ty + 8 * j;
        uint32_t h = pack_h2(tile[2 * k2l][tx], tile[2 * k2l + 1][tx]);
        dst[(size_t)(c0 + tx) * (K / 2) + (k0 >> 1) + p16(k2l)] = h;
    }
}

// ---------------------------------------------------------------------------
// fp16 GEMM, 2-stage cp.async double-buffered. C[M,N](f32) = A[M,K]*Bt[N,K]^T.
// chunk 32 u32 (64 halves), stride 48 (validated). 8 warps in 4m x 2n grid,
// warp tile 32x64. Copy for chunk i+1 overlaps compute of chunk i.
// smem: 2 stages x 2 tiles x 128 x 48 x 4 = 98,304 B -> 2 CTAs/SM.
// ---------------------------------------------------------------------------
#define GSG 48
#define STAGE_U32 (128 * GSG)
#define GEMM_SMEM_BYTES (4 * STAGE_U32 * 4)

__global__ __launch_bounds__(256, 2) void gemm_h_kernel(
    const uint32_t* __restrict__ A, const uint32_t* __restrict__ Bt,
    float* __restrict__ C, int M, int N)
{
    extern __shared__ uint32_t us[];
    uint32_t* As = us;                    // [2][128][48]
    uint32_t* Bs = us + 2 * STAGE_U32;    // [2][128][48]

    const int tid  = threadIdx.x;
    const int w    = tid >> 5;
    const int lane = tid & 31;
    const int g = lane >> 2;
    const int t = lane & 3;
    const int m0 = blockIdx.y * 128;
    const int n0 = blockIdx.x * 128;
    const int wm = (w & 3) * 32;
    const int wn = (w >> 2) * 64;
    const int K2 = 512;

    // per-thread copy slots: 4 uint4 for A + 4 for B per stage
    const int cp_r0 = tid >> 3;           // 0..31 base row (x4 via i)
    const int cp_c4 = (tid & 7) * 4;      // 0,4,...,28

    float acc[2][8][4];
#pragma unroll
    for (int mg = 0; mg < 2; mg++)
#pragma unroll
        for (int nn = 0; nn < 8; nn++)
#pragma unroll
            for (int v = 0; v < 4; v++) acc[mg][nn][v] = 0.f;

    // prologue: stage 0 in flight
    {
#pragma unroll
        for (int i = 0; i < 4; i++) {
            int rr = cp_r0 + i * 32;
            cp16(&As[rr * GSG + cp_c4], &A[(size_t)(m0 + rr) * K2 + cp_c4]);
            cp16(&Bs[rr * GSG + cp_c4], &Bt[(size_t)(n0 + rr) * K2 + cp_c4]);
        }
        cp_commit();
    }

    int buf = 0;
    for (int k0 = 0; k0 < K2; k0 += 32) {
        cp_wait0();
        __syncthreads();

        if (k0 + 32 < K2) {
            const int nb = buf ^ 1;
#pragma unroll
            for (int i = 0; i < 4; i++) {
                int rr = cp_r0 + i * 32;
                cp16(&As[nb * STAGE_U32 + rr * GSG + cp_c4],
                     &A[(size_t)(m0 + rr) * K2 + k0 + 32 + cp_c4]);
                cp16(&Bs[nb * STAGE_U32 + rr * GSG + cp_c4],
                     &Bt[(size_t)(n0 + rr) * K2 + k0 + 32 + cp_c4]);
            }
            cp_commit();
        }

        const uint32_t* as = &As[buf * STAGE_U32];
        const uint32_t* bs = &Bs[buf * STAGE_U32];
#pragma unroll
        for (int kp = 0; kp < 2; kp++) {
            uint4 Ag[2][2];
#pragma unroll
            for (int mg = 0; mg < 2; mg++) {
                Ag[mg][0] = *(const uint4*)&as[(wm + mg * 16 + g)     * GSG + kp * 16 + 4 * t];
                Ag[mg][1] = *(const uint4*)&as[(wm + mg * 16 + g + 8) * GSG + kp * 16 + 4 * t];
            }
#pragma unroll
            for (int nn = 0; nn < 8; nn++) {
                uint4 Bv = *(const uint4*)&bs[(wn + nn * 8 + g) * GSG + kp * 16 + 4 * t];
#pragma unroll
                for (int mg = 0; mg < 2; mg++) {
                    mma_h(acc[mg][nn], Ag[mg][0].x, Ag[mg][1].x, Ag[mg][0].y, Ag[mg][1].y,
                          Bv.x, Bv.y);
                    mma_h(acc[mg][nn], Ag[mg][0].z, Ag[mg][1].z, Ag[mg][0].w, Ag[mg][1].w,
                          Bv.z, Bv.w);
                }
            }
        }
        buf ^= 1;
    }

#pragma unroll
    for (int mg = 0; mg < 2; mg++) {
        const int row0 = m0 + wm + mg * 16 + g;
        const int row1 = row0 + 8;
#pragma unroll
        for (int nn = 0; nn < 8; nn++) {
            const int col = n0 + wn + nn * 8 + 2 * t;
            *(float2*)&C[(size_t)row0 * N + col] = make_float2(acc[mg][nn][0], acc[mg][nn][1]);
            *(float2*)&C[(size_t)row1 * N + col] = make_float2(acc[mg][nn][2], acc[mg][nn][3]);
        }
    }
}

// ---------------------------------------------------------------------------
// LayerNorm(q,k)*D^-0.25 + split. q/k -> half perm16; v -> f32 (validated)
// ---------------------------------------------------------------------------
__global__ __launch_bounds__(256) void ln_split_h_kernel(
    const float* __restrict__ qkv,
    const float* __restrict__ q_scale, const float* __restrict__ q_bias,
    const float* __restrict__ k_scale, const float* __restrict__ k_bias,
    uint32_t* __restrict__ q_h, uint32_t* __restrict__ k_h, float* __restrict__ v_t)
{
    const int wid  = (blockIdx.x * blockDim.x + threadIdx.x) >> 5;
    const int lane = threadIdx.x & 31;
    const int h = wid & (HEADS - 1);
    const int m = wid >> 4;
    const int b = m >> 11;
    const int l = m & (L_SEQ - 1);

    const float* row = qkv + (size_t)m * THREEC;
    const size_t tok = ((size_t)(b * HEADS + h)) * L_SEQ + l;
    const int d0 = 2 * lane, d1 = 2 * lane + 1;
    const int ppos = (lane & 16) | p16(lane & 15);

    {
        float x0 = row[h * HD + d0];
        float x1 = row[h * HD + d1];
        float s = x0 + x1;
#pragma unroll
        for (int o = 16; o > 0; o >>= 1) s += __shfl_xor_sync(0xffffffffu, s, o);
        float mu = s * (1.f / HD);
        float e0 = x0 - mu, e1 = x1 - mu;
        float vs = e0 * e0 + e1 * e1;
#pragma unroll
        for (int o = 16; o > 0; o >>= 1) vs += __shfl_xor_sync(0xffffffffu, vs, o);
        float rstd = rsqrtf(vs * (1.f / HD) + 1e-6f);
        float y0 = (e0 * rstd * q_scale[d0] + q_bias[d0]) * INV4;
        float y1 = (e1 * rstd * q_scale[d1] + q_bias[d1]) * INV4;
        q_h[tok * 32 + ppos] = pack_h2(y0, y1);
    }
    {
        float x0 = row[CDIM + h * HD + d0];
        float x1 = row[CDIM + h * HD + d1];
        float s = x0 + x1;
#pragma unroll
        for (int o = 16; o > 0; o >>= 1) s += __shfl_xor_sync(0xffffffffu, s, o);
        float mu = s * (1.f / HD);
        float e0 = x0 - mu, e1 = x1 - mu;
        float vs = e0 * e0 + e1 * e1;
#pragma unroll
        for (int o = 16; o > 0; o >>= 1) vs += __shfl_xor_sync(0xffffffffu, vs, o);
        float rstd = rsqrtf(vs * (1.f / HD) + 1e-6f);
        float y0 = (e0 * rstd * k_scale[d0] + k_bias[d0]) * INV4;
        float y1 = (e1 * rstd * k_scale[d1] + k_bias[d1]) * INV4;
        k_h[tok * 32 + ppos] = pack_h2(y0, y1);
    }
    v_t[tok * HD + lane]      = __uint_as_float(f2tf32(row[2 * CDIM + h * HD + lane]));
    v_t[tok * HD + lane + 32] = __uint_as_float(f2tf32(row[2 * CDIM + h * HD + lane + 32]));
}

// ---------------------------------------------------------------------------
// fp16 flash attention (R13 verbatim, passing config)
// ---------------------------------------------------------------------------
#define GS 48
#define ATTN_SMEM_BYTES (256 * GS * 4)

__global__ __launch_bounds__(256, 2) void attn_h2_kernel(
    const uint32_t* __restrict__ q_h, const uint32_t* __restrict__ k_h,
    const float* __restrict__ v_t, uint32_t* __restrict__ atth)
{
    extern __shared__ uint32_t us[];
    uint32_t* Qh = us;                    // [128][GS]
    uint32_t* Kh = us + 128 * GS;         // [64][GS]
    uint32_t* Vt = us + 192 * GS;         // [64][GS]

    const int tid  = threadIdx.x;
    const int w    = tid >> 5;
    const int lane = tid & 31;
    const int g = lane >> 2;
    const int t = lane & 3;
    const int bh = blockIdx.y;
    const int q0 = blockIdx.x * 128;
    const int qr0 = w * 16;

    const uint32_t* Qp = q_h + (size_t)bh * L_SEQ * 32;
    const uint32_t* Kp = k_h + (size_t)bh * L_SEQ * 32;
    const float*    Vp = v_t + (size_t)bh * L_SEQ * HD;

#pragma unroll
    for (int i = 0; i < 4; i++) {
        int id = i * 256 + tid;
        int rr = id >> 3;
        int c4 = (id & 7) * 4;
        *(uint4*)&Qh[rr * GS + c4] = *(const uint4*)&Qp[(size_t)(q0 + rr) * 32 + c4];
    }

    float o[8][4];
#pragma unroll
    for (int nn = 0; nn < 8; nn++)
#pragma unroll
        for (int v = 0; v < 4; v++) o[nn][v] = 0.f;
    float mrow0 = -1e30f, mrow1 = -1e30f;
    float lrow0 = 0.f,    lrow1 = 0.f;

    for (int kt = 0; kt < L_SEQ; kt += 64) {
        __syncthreads();
#pragma unroll
        for (int i = 0; i < 2; i++) {
            int id = i * 256 + tid;
            int rr = id >> 3;
            int c4 = (id & 7) * 4;
            *(uint4*)&Kh[rr * GS + c4] = *(const uint4*)&Kp[(size_t)(kt + rr) * 32 + c4];
        }
#pragma unroll
        for (int i = 0; i < 4; i++) {
            int idx = tid + i * 256;
            int key = idx & 63;
            int dg  = (idx >> 6) << 2;
            float4 mv = *(const float4*)&Vp[(size_t)(kt + key) * HD + dg];
            float4 pr;
            pr.x = __shfl_xor_sync(0xffffffffu, mv.x, 1);
            pr.y = __shfl_xor_sync(0xffffffffu, mv.y, 1);
            pr.z = __shfl_xor_sync(0xffffffffu, mv.z, 1);
            pr.w = __shfl_xor_sync(0xffffffffu, mv.w, 1);
            int key2 = key >> 1;
            int pos = (key2 & 16) | p16(key2 & 15);
            if (!(key & 1)) {
                Vt[(dg + 0) * GS + pos] = pack_h2(mv.x, pr.x);
                Vt[(dg + 1) * GS + pos] = pack_h2(mv.y, pr.y);
            } else {
                Vt[(dg + 2) * GS + pos] = pack_h2(pr.z, mv.z);
                Vt[(dg + 3) * GS + pos] = pack_h2(pr.w, mv.w);
            }
        }
        __syncthreads();

        float s[8][4];
#pragma unroll
        for (int nn = 0; nn < 8; nn++)
#pragma unroll
            for (int v = 0; v < 4; v++) s[nn][v] = 0.f;

#pragma unroll
        for (int kp = 0; kp < 2; kp++) {
            uint4 Qg  = *(const uint4*)&Qh[(qr0 + g)     * GS + kp * 16 + 4 * t];
            uint4 Qg8 = *(const uint4*)&Qh[(qr0 + g + 8) * GS + kp * 16 + 4 * t];
#pragma unroll
            for (int nn = 0; nn < 8; nn++) {
                uint4 Kv = *(const uint4*)&Kh[(nn * 8 + g) * GS + kp * 16 + 4 * t];
                mma_h(s[nn], Qg.x, Qg8.x, Qg.y, Qg8.y, Kv.x, Kv.y);
                mma_h(s[nn], Qg.z, Qg8.z, Qg.w, Qg8.w, Kv.z, Kv.w);
            }
        }

        float mx0 = -1e30f, mx1 = -1e30f;
#pragma unroll
        for (int nn = 0; nn < 8; nn++) {
            mx0 = fmaxf(mx0, fmaxf(s[nn][0], s[nn][1]));
            mx1 = fmaxf(mx1, fmaxf(s[nn][2], s[nn][3]));
        }
        mx0 = fmaxf(mx0, __shfl_xor_sync(0xffffffffu, mx0, 1));
        mx0 = fmaxf(mx0, __shfl_xor_sync(0xffffffffu, mx0, 2));
        mx1 = fmaxf(mx1, __shfl_xor_sync(0xffffffffu, mx1, 1));
        mx1 = fmaxf(mx1, __shfl_xor_sync(0xffffffffu, mx1, 2));

        float mn0 = fmaxf(mrow0, mx0);
        float mn1 = fmaxf(mrow1, mx1);
        float alpha0 = __expf(mrow0 - mn0);
        float alpha1 = __expf(mrow1 - mn1);
        mrow0 = mn0; mrow1 = mn1;

        float rs0 = 0.f, rs1 = 0.f;
#pragma unroll
        for (int nn = 0; nn < 8; nn++) {
            s[nn][0] = __expf(s[nn][0] - mn0);
            s[nn][1] = __expf(s[nn][1] - mn0);
            s[nn][2] = __expf(s[nn][2] - mn1);
            s[nn][3] = __expf(s[nn][3] - mn1);
            rs0 += s[nn][0] + s[nn][1];
            rs1 += s[nn][2] + s[nn][3];
        }
        rs0 += __shfl_xor_sync(0xffffffffu, rs0, 1);
        rs0 += __shfl_xor_sync(0xffffffffu, rs0, 2);
        rs1 += __shfl_xor_sync(0xffffffffu, rs1, 1);
        rs1 += __shfl_xor_sync(0xffffffffu, rs1, 2);
        lrow0 = lrow0 * alpha0 + rs0;
        lrow1 = lrow1 * alpha1 + rs1;

#pragma unroll
        for (int nn = 0; nn < 8; nn++) {
            o[nn][0] *= alpha0; o[nn][1] *= alpha0;
            o[nn][2] *= alpha1; o[nn][3] *= alpha1;
        }

#pragma unroll
        for (int kp = 0; kp < 2; kp++) {
            uint32_t ae0 = pack_h2(s[4 * kp + 0][0], s[4 * kp + 0][1]);
            uint32_t ae1 = pack_h2(s[4 * kp + 0][2], s[4 * kp + 0][3]);
            uint32_t ae2 = pack_h2(s[4 * kp + 1][0], s[4 * kp + 1][1]);
            uint32_t ae3 = pack_h2(s[4 * kp + 1][2], s[4 * kp + 1][3]);
            uint32_t ao0 = pack_h2(s[4 * kp + 2][0], s[4 * kp + 2][1]);
            uint32_t ao1 = pack_h2(s[4 * kp + 2][2], s[4 * kp + 2][3]);
            uint32_t ao2 = pack_h2(s[4 * kp + 3][0], s[4 * kp + 3][1]);
            uint32_t ao3 = pack_h2(s[4 * kp + 3][2], s[4 * kp + 3][3]);
#pragma unroll
            for (int nn = 0; nn < 8; nn++) {
                uint4 Vv = *(const uint4*)&Vt[(nn * 8 + g) * GS + kp * 16 + 4 * t];
                mma_h(o[nn], ae0, ae1, ae2, ae3, Vv.x, Vv.y);
                mma_h(o[nn], ao0, ao1, ao2, ao3, Vv.z, Vv.w);
            }
        }
    }

    const int b_ = bh >> 4;
    const int h  = bh & (HEADS - 1);
    const float inv0 = 1.f / lrow0;
    const float inv1 = 1.f / lrow1;
    const int tok0 = b_ * L_SEQ + q0 + qr0 + g;
    const int tok1 = tok0 + 8;
#pragma unroll
    for (int nn = 0; nn < 8; nn++) {
        int pos = h * 32 + ((nn >> 2) << 4) + 4 * t + (nn & 3);
        atth[(size_t)tok0 * 512 + pos] = pack_h2(o[nn][0] * inv0, o[nn][1] * inv0);
        atth[(size_t)tok1 * 512 + pos] = pack_h2(o[nn][2] * inv1, o[nn][3] * inv1);
    }
}

// ---------------------------------------------------------------------------
// Host launch
// ---------------------------------------------------------------------------
extern "C" void kernel_launch(void* const* d_in, const int* in_sizes, int n_in,
                              void* d_out, int out_size)
{
    const float* x       = (const float*)d_in[0];
    const float* w_qkv   = (const float*)d_in[1];
    const float* w_out   = (const float*)d_in[2];
    const float* q_scale = (const float*)d_in[3];
    const float* q_bias  = (const float*)d_in[4];
    const float* k_scale = (const float*)d_in[5];
    const float* k_bias  = (const float*)d_in[6];
    float* out = (float*)d_out;

    void *p_qkv, *p_qh, *p_kh, *p_v, *p_xh, *p_wh, *p_worh, *p_atth;
    cudaGetSymbolAddress(&p_qkv, g_qkv);
    cudaGetSymbolAddress(&p_qh, g_qh);
    cudaGetSymbolAddress(&p_kh, g_kh);
    cudaGetSymbolAddress(&p_v, g_v);
    cudaGetSymbolAddress(&p_xh, g_xh);
    cudaGetSymbolAddress(&p_wh, g_wh);
    cudaGetSymbolAddress(&p_worh, g_worh);
    cudaGetSymbolAddress(&p_atth, g_atth);

    // 0) prep
    cvt_perm_kernel<<<(MTOT * 256 + 255) / 256, 256>>>(x, (uint32_t*)p_xh, MTOT * 256);
    transpose_cvt_perm_kernel<<<dim3(THREEC / 32, CDIM / 32), 256>>>(
        w_qkv, (uint32_t*)p_wh, CDIM, THREEC);
    transpose_cvt_perm_kernel<<<dim3(CDIM / 32, CDIM / 32), 256>>>(
        w_out, (uint32_t*)p_worh, CDIM, CDIM);

    // 1) QKV projection
    cudaFuncSetAttribute(gemm_h_kernel, cudaFuncAttributeMaxDynamicSharedMemorySize,
                         GEMM_SMEM_BYTES);
    gemm_h_kernel<<<dim3(THREEC / 128, MTOT / 128), 256, GEMM_SMEM_BYTES>>>(
        (const uint32_t*)p_xh, (const uint32_t*)p_wh, (float*)p_qkv, MTOT, THREEC);

    // 2) QK LayerNorm + split (q/k half perm16, v f32)
    ln_split_h_kernel<<<(MTOT * HEADS) / 8, 256>>>(
        (const float*)p_qkv, q_scale, q_bias, k_scale, k_bias,
        (uint32_t*)p_qh, (uint32_t*)p_kh, (float*)p_v);

    // 3) Flash attention -> half perm16 directly
    cudaFuncSetAttribute(attn_h2_kernel, cudaFuncAttributeMaxDynamicSharedMemorySize,
                         ATTN_SMEM_BYTES);
    attn_h2_kernel<<<dim3(L_SEQ / 128, BATCH * HEADS), 256, ATTN_SMEM_BYTES>>>(
        (const uint32_t*)p_qh, (const uint32_t*)p_kh, (const float*)p_v,
        (uint32_t*)p_atth);

    // 4) Output projection
    gemm_h_kernel<<<dim3(CDIM / 128, MTOT / 128), 256, GEMM_SMEM_BYTES>>>(
        (const uint32_t*)p_atth, (const uint32_t*)p_worh, out, MTOT, CDIM);
}

// round 15
// speedup vs baseline: 2.4599x; 1.2081x over previous
#include <cuda_runtime.h>
#include <cuda_fp16.h>
#include <cstdint>

// Problem constants
#define BATCH 2
#define L_SEQ 2048
#define CDIM  1024
#define HEADS 16
#define HD    64
#define MTOT  4096
#define THREEC 3072
#define INV4  0.3535533905932738f   // 64^-0.25

// ---------------------------------------------------------------------------
// Scratch (device globals; no allocation allowed)
// token count = B*H*L = 65536 = MTOT*16; q/k/v/vt sized MTOT*512 u32 each.
// ---------------------------------------------------------------------------
__device__ __align__(16) float    g_qkv [(size_t)MTOT * THREEC];  // f32 QKV out
__device__ __align__(16) uint32_t g_qh  [(size_t)MTOT * 512];     // q half perm16 [B,H,L]
__device__ __align__(16) uint32_t g_kh  [(size_t)MTOT * 512];     // k half perm16 [B,H,L]
__device__ __align__(16) uint32_t g_vh  [(size_t)MTOT * 512];     // v half natural [B,H,L][d2]
__device__ __align__(16) uint32_t g_vt  [(size_t)MTOT * 512];     // v^T half [B,H][d][key2 perm16]
__device__ __align__(16) uint32_t g_xh  [(size_t)MTOT * 512];     // x half perm16
__device__ __align__(16) uint32_t g_wh  [(size_t)THREEC * 512];   // w_qkv^T half perm16
__device__ __align__(16) uint32_t g_worh[(size_t)CDIM * 512];     // w_out^T half perm16
__device__ __align__(16) uint32_t g_atth[(size_t)MTOT * 512];     // attn out half perm16

// ---------------------------------------------------------------------------
// Helpers
// ---------------------------------------------------------------------------
__device__ __forceinline__ int p16(int c) { return ((c & 3) << 2) | (c >> 2); }

__device__ __forceinline__ uint32_t pack_h2(float a, float b) {
    __half2 h = __floats2half2_rn(a, b);     // low = a, high = b
    return *reinterpret_cast<uint32_t*>(&h);
}

__device__ __forceinline__ void mma_h(float* d,
                                      uint32_t a0, uint32_t a1, uint32_t a2, uint32_t a3,
                                      uint32_t b0, uint32_t b1) {
    asm volatile(
        "mma.sync.aligned.m16n8k16.row.col.f32.f16.f16.f32 "
        "{%0,%1,%2,%3}, {%4,%5,%6,%7}, {%8,%9}, {%0,%1,%2,%3};\n"
        : "+f"(d[0]), "+f"(d[1]), "+f"(d[2]), "+f"(d[3])
        : "r"(a0), "r"(a1), "r"(a2), "r"(a3), "r"(b0), "r"(b1));
}

__device__ __forceinline__ void cp16(void* smem, const void* gmem) {
    uint32_t s = (uint32_t)__cvta_generic_to_shared(smem);
    asm volatile("cp.async.ca.shared.global [%0], [%1], 16;" :: "r"(s), "l"(gmem));
}
__device__ __forceinline__ void cp_commit() { asm volatile("cp.async.commit_group;"); }
__device__ __forceinline__ void cp_wait0()  { asm volatile("cp.async.wait_group 0;"); }

// ---------------------------------------------------------------------------
// Prep: f32 [R][1024] -> half u32 [R][512] with perm16 along K (validated)
// ---------------------------------------------------------------------------
__global__ __launch_bounds__(256) void cvt_perm_kernel(
    const float* __restrict__ src, uint32_t* __restrict__ dst, int n_f4)
{
    int i = blockIdx.x * blockDim.x + threadIdx.x;
    if (i >= n_f4) return;
    float4 v = ((const float4*)src)[i];
    int row = i >> 8;
    int f4  = i & 255;
    int k2a = 2 * f4, k2b = 2 * f4 + 1;
    int base = row * 512;
    dst[base + (k2a & ~15) + p16(k2a & 15)] = pack_h2(v.x, v.y);
    dst[base + (k2b & ~15) + p16(k2b & 15)] = pack_h2(v.z, v.w);
}

// f32 [K][C] -> half u32 [C][K/2] (transposed) with perm16 along K (validated)
__global__ __launch_bounds__(256) void transpose_cvt_perm_kernel(
    const float* __restrict__ src, uint32_t* __restrict__ dst, int K, int C)
{
    __shared__ float tile[32][33];
    const int c0 = blockIdx.x * 32, k0 = blockIdx.y * 32;
    const int tx = threadIdx.x & 31;
    const int ty = threadIdx.x >> 5;
#pragma unroll
    for (int j = 0; j < 4; j++)
        tile[ty + j * 8][tx] = src[(size_t)(k0 + ty + j * 8) * C + c0 + tx];
    __syncthreads();
#pragma unroll
    for (int j = 0; j < 2; j++) {
        int k2l = ty + 8 * j;
        uint32_t h = pack_h2(tile[2 * k2l][tx], tile[2 * k2l + 1][tx]);
        dst[(size_t)(c0 + tx) * (K / 2) + (k0 >> 1) + p16(k2l)] = h;
    }
}

// ---------------------------------------------------------------------------
// V transpose: vh [bh][L][32 u32 d2-natural] -> vt [bh][64 d][L/2 u32],
// columns arranged (key2&16)|p16(key2&15) within each 32-block (= the exact
// layout attention's Vt smem expects, enabling plain uint4 fills).
// ---------------------------------------------------------------------------
__global__ __launch_bounds__(256) void transpose_v_kernel(
    const uint32_t* __restrict__ vh, uint32_t* __restrict__ vt)
{
    __shared__ uint32_t tile[64][33];
    const int bh = blockIdx.y;
    const int t0 = blockIdx.x * 64;
    const int tid = threadIdx.x;

    const uint32_t* src = vh + (size_t)bh * L_SEQ * 32 + (size_t)t0 * 32;
#pragma unroll
    for (int i = 0; i < 8; i++) {
        int idx = tid + i * 256;
        int tok = idx >> 5;
        int d2  = idx & 31;
        tile[tok][d2] = src[tok * 32 + d2];
    }
    __syncthreads();

    uint32_t* dst = vt + (size_t)bh * 64 * (L_SEQ / 2) + (t0 >> 1);
#pragma unroll
    for (int i = 0; i < 8; i++) {
        int idx = tid + i * 256;
        int d   = idx >> 5;          // 0..63
        int k2l = idx & 31;          // 0..31
        uint32_t w0 = tile[2 * k2l][d >> 1];      // token 2*k2l, d-pair
        uint32_t w1 = tile[2 * k2l + 1][d >> 1];  // token 2*k2l+1
        uint32_t lo = (d & 1) ? (w0 >> 16) : (w0 & 0xFFFFu);
        uint32_t hi = (d & 1) ? (w1 & 0xFFFF0000u) : (w1 << 16);
        int pos = (k2l & 16) | p16(k2l & 15);
        dst[(size_t)d * (L_SEQ / 2) + pos] = lo | hi;
    }
}

// ---------------------------------------------------------------------------
// fp16 GEMM, 2-stage cp.async double-buffered (R14 verbatim).
// ---------------------------------------------------------------------------
#define GSG 48
#define STAGE_U32 (128 * GSG)
#define GEMM_SMEM_BYTES (4 * STAGE_U32 * 4)

__global__ __launch_bounds__(256, 2) void gemm_h_kernel(
    const uint32_t* __restrict__ A, const uint32_t* __restrict__ Bt,
    float* __restrict__ C, int M, int N)
{
    extern __shared__ uint32_t us[];
    uint32_t* As = us;                    // [2][128][48]
    uint32_t* Bs = us + 2 * STAGE_U32;    // [2][128][48]

    const int tid  = threadIdx.x;
    const int w    = tid >> 5;
    const int lane = tid & 31;
    const int g = lane >> 2;
    const int t = lane & 3;
    const int m0 = blockIdx.y * 128;
    const int n0 = blockIdx.x * 128;
    const int wm = (w & 3) * 32;
    const int wn = (w >> 2) * 64;
    const int K2 = 512;

    const int cp_r0 = tid >> 3;
    const int cp_c4 = (tid & 7) * 4;

    float acc[2][8][4];
#pragma unroll
    for (int mg = 0; mg < 2; mg++)
#pragma unroll
        for (int nn = 0; nn < 8; nn++)
#pragma unroll
            for (int v = 0; v < 4; v++) acc[mg][nn][v] = 0.f;

    {
#pragma unroll
        for (int i = 0; i < 4; i++) {
            int rr = cp_r0 + i * 32;
            cp16(&As[rr * GSG + cp_c4], &A[(size_t)(m0 + rr) * K2 + cp_c4]);
            cp16(&Bs[rr * GSG + cp_c4], &Bt[(size_t)(n0 + rr) * K2 + cp_c4]);
        }
        cp_commit();
    }

    int buf = 0;
    for (int k0 = 0; k0 < K2; k0 += 32) {
        cp_wait0();
        __syncthreads();

        if (k0 + 32 < K2) {
            const int nb = buf ^ 1;
#pragma unroll
            for (int i = 0; i < 4; i++) {
                int rr = cp_r0 + i * 32;
                cp16(&As[nb * STAGE_U32 + rr * GSG + cp_c4],
                     &A[(size_t)(m0 + rr) * K2 + k0 + 32 + cp_c4]);
                cp16(&Bs[nb * STAGE_U32 + rr * GSG + cp_c4],
                     &Bt[(size_t)(n0 + rr) * K2 + k0 + 32 + cp_c4]);
            }
            cp_commit();
        }

        const uint32_t* as = &As[buf * STAGE_U32];
        const uint32_t* bs = &Bs[buf * STAGE_U32];
#pragma unroll
        for (int kp = 0; kp < 2; kp++) {
            uint4 Ag[2][2];
#pragma unroll
            for (int mg = 0; mg < 2; mg++) {
                Ag[mg][0] = *(const uint4*)&as[(wm + mg * 16 + g)     * GSG + kp * 16 + 4 * t];
                Ag[mg][1] = *(const uint4*)&as[(wm + mg * 16 + g + 8) * GSG + kp * 16 + 4 * t];
            }
#pragma unroll
            for (int nn = 0; nn < 8; nn++) {
                uint4 Bv = *(const uint4*)&bs[(wn + nn * 8 + g) * GSG + kp * 16 + 4 * t];
#pragma unroll
                for (int mg = 0; mg < 2; mg++) {
                    mma_h(acc[mg][nn], Ag[mg][0].x, Ag[mg][1].x, Ag[mg][0].y, Ag[mg][1].y,
                          Bv.x, Bv.y);
                    mma_h(acc[mg][nn], Ag[mg][0].z, Ag[mg][1].z, Ag[mg][0].w, Ag[mg][1].w,
                          Bv.z, Bv.w);
                }
            }
        }
        buf ^= 1;
    }

#pragma unroll
    for (int mg = 0; mg < 2; mg++) {
        const int row0 = m0 + wm + mg * 16 + g;
        const int row1 = row0 + 8;
#pragma unroll
        for (int nn = 0; nn < 8; nn++) {
            const int col = n0 + wn + nn * 8 + 2 * t;
            *(float2*)&C[(size_t)row0 * N + col] = make_float2(acc[mg][nn][0], acc[mg][nn][1]);
            *(float2*)&C[(size_t)row1 * N + col] = make_float2(acc[mg][nn][2], acc[mg][nn][3]);
        }
    }
}

// ---------------------------------------------------------------------------
// LayerNorm(q,k)*D^-0.25 + split. q/k -> half perm16; v -> half natural d2.
// ---------------------------------------------------------------------------
__global__ __launch_bounds__(256) void ln_split_h_kernel(
    const float* __restrict__ qkv,
    const float* __restrict__ q_scale, const float* __restrict__ q_bias,
    const float* __restrict__ k_scale, const float* __restrict__ k_bias,
    uint32_t* __restrict__ q_h, uint32_t* __restrict__ k_h, uint32_t* __restrict__ v_h)
{
    const int wid  = (blockIdx.x * blockDim.x + threadIdx.x) >> 5;
    const int lane = threadIdx.x & 31;
    const int h = wid & (HEADS - 1);
    const int m = wid >> 4;
    const int b = m >> 11;
    const int l = m & (L_SEQ - 1);

    const float* row = qkv + (size_t)m * THREEC;
    const size_t tok = ((size_t)(b * HEADS + h)) * L_SEQ + l;
    const int d0 = 2 * lane, d1 = 2 * lane + 1;
    const int ppos = (lane & 16) | p16(lane & 15);

    {
        float x0 = row[h * HD + d0];
        float x1 = row[h * HD + d1];
        float s = x0 + x1;
#pragma unroll
        for (int o = 16; o > 0; o >>= 1) s += __shfl_xor_sync(0xffffffffu, s, o);
        float mu = s * (1.f / HD);
        float e0 = x0 - mu, e1 = x1 - mu;
        float vs = e0 * e0 + e1 * e1;
#pragma unroll
        for (int o = 16; o > 0; o >>= 1) vs += __shfl_xor_sync(0xffffffffu, vs, o);
        float rstd = rsqrtf(vs * (1.f / HD) + 1e-6f);
        float y0 = (e0 * rstd * q_scale[d0] + q_bias[d0]) * INV4;
        float y1 = (e1 * rstd * q_scale[d1] + q_bias[d1]) * INV4;
        q_h[tok * 32 + ppos] = pack_h2(y0, y1);
    }
    {
        float x0 = row[CDIM + h * HD + d0];
        float x1 = row[CDIM + h * HD + d1];
        float s = x0 + x1;
#pragma unroll
        for (int o = 16; o > 0; o >>= 1) s += __shfl_xor_sync(0xffffffffu, s, o);
        float mu = s * (1.f / HD);
        float e0 = x0 - mu, e1 = x1 - mu;
        float vs = e0 * e0 + e1 * e1;
#pragma unroll
        for (int o = 16; o > 0; o >>= 1) vs += __shfl_xor_sync(0xffffffffu, vs, o);
        float rstd = rsqrtf(vs * (1.f / HD) + 1e-6f);
        float y0 = (e0 * rstd * k_scale[d0] + k_bias[d0]) * INV4;
        float y1 = (e1 * rstd * k_scale[d1] + k_bias[d1]) * INV4;
        k_h[tok * 32 + ppos] = pack_h2(y0, y1);
    }
    v_h[tok * 32 + lane] = pack_h2(row[2 * CDIM + h * HD + d0],
                                   row[2 * CDIM + h * HD + d1]);
}

// ---------------------------------------------------------------------------
// fp16 flash attention. Q/K/Vt all pre-packed in gmem -> all fills are plain
// uint4 copies. Everything else R14-verbatim.
// ---------------------------------------------------------------------------
#define GS 48
#define ATTN_SMEM_BYTES (256 * GS * 4)

__global__ __launch_bounds__(256, 2) void attn_h2_kernel(
    const uint32_t* __restrict__ q_h, const uint32_t* __restrict__ k_h,
    const uint32_t* __restrict__ v_t, uint32_t* __restrict__ atth)
{
    extern __shared__ uint32_t us[];
    uint32_t* Qh = us;                    // [128][GS]
    uint32_t* Kh = us + 128 * GS;         // [64][GS]
    uint32_t* Vt = us + 192 * GS;         // [64][GS]

    const int tid  = threadIdx.x;
    const int w    = tid >> 5;
    const int lane = tid & 31;
    const int g = lane >> 2;
    const int t = lane & 3;
    const int bh = blockIdx.y;
    const int q0 = blockIdx.x * 128;
    const int qr0 = w * 16;

    const uint32_t* Qp = q_h + (size_t)bh * L_SEQ * 32;
    const uint32_t* Kp = k_h + (size_t)bh * L_SEQ * 32;
    const uint32_t* Vp = v_t + (size_t)bh * 64 * (L_SEQ / 2);

#pragma unroll
    for (int i = 0; i < 4; i++) {
        int id = i * 256 + tid;
        int rr = id >> 3;
        int c4 = (id & 7) * 4;
        *(uint4*)&Qh[rr * GS + c4] = *(const uint4*)&Qp[(size_t)(q0 + rr) * 32 + c4];
    }

    float o[8][4];
#pragma unroll
    for (int nn = 0; nn < 8; nn++)
#pragma unroll
        for (int v = 0; v < 4; v++) o[nn][v] = 0.f;
    float mrow0 = -1e30f, mrow1 = -1e30f;
    float lrow0 = 0.f,    lrow1 = 0.f;

    for (int kt = 0; kt < L_SEQ; kt += 64) {
        __syncthreads();
        // K tile: plain uint4 copies
#pragma unroll
        for (int i = 0; i < 2; i++) {
            int id = i * 256 + tid;
            int rr = id >> 3;
            int c4 = (id & 7) * 4;
            *(uint4*)&Kh[rr * GS + c4] = *(const uint4*)&Kp[(size_t)(kt + rr) * 32 + c4];
        }
        // V tile: plain uint4 copies from pre-transposed gmem
#pragma unroll
        for (int i = 0; i < 2; i++) {
            int id = i * 256 + tid;
            int rr = id >> 3;                 // d 0..63
            int c4 = (id & 7) * 4;
            *(uint4*)&Vt[rr * GS + c4] =
                *(const uint4*)&Vp[(size_t)rr * (L_SEQ / 2) + (kt >> 1) + c4];
        }
        __syncthreads();

        // S = Q K^T (fp16)
        float s[8][4];
#pragma unroll
        for (int nn = 0; nn < 8; nn++)
#pragma unroll
            for (int v = 0; v < 4; v++) s[nn][v] = 0.f;

#pragma unroll
        for (int kp = 0; kp < 2; kp++) {
            uint4 Qg  = *(const uint4*)&Qh[(qr0 + g)     * GS + kp * 16 + 4 * t];
            uint4 Qg8 = *(const uint4*)&Qh[(qr0 + g + 8) * GS + kp * 16 + 4 * t];
#pragma unroll
            for (int nn = 0; nn < 8; nn++) {
                uint4 Kv = *(const uint4*)&Kh[(nn * 8 + g) * GS + kp * 16 + 4 * t];
                mma_h(s[nn], Qg.x, Qg8.x, Qg.y, Qg8.y, Kv.x, Kv.y);
                mma_h(s[nn], Qg.z, Qg8.z, Qg.w, Qg8.w, Kv.z, Kv.w);
            }
        }

        // online softmax (rows g, g+8; quad reductions)
        float mx0 = -1e30f, mx1 = -1e30f;
#pragma unroll
        for (int nn = 0; nn < 8; nn++) {
            mx0 = fmaxf(mx0, fmaxf(s[nn][0], s[nn][1]));
            mx1 = fmaxf(mx1, fmaxf(s[nn][2], s[nn][3]));
        }
        mx0 = fmaxf(mx0, __shfl_xor_sync(0xffffffffu, mx0, 1));
        mx0 = fmaxf(mx0, __shfl_xor_sync(0xffffffffu, mx0, 2));
        mx1 = fmaxf(mx1, __shfl_xor_sync(0xffffffffu, mx1, 1));
        mx1 = fmaxf(mx1, __shfl_xor_sync(0xffffffffu, mx1, 2));

        float mn0 = fmaxf(mrow0, mx0);
        float mn1 = fmaxf(mrow1, mx1);
        float alpha0 = __expf(mrow0 - mn0);
        float alpha1 = __expf(mrow1 - mn1);
        mrow0 = mn0; mrow1 = mn1;

        float rs0 = 0.f, rs1 = 0.f;
#pragma unroll
        for (int nn = 0; nn < 8; nn++) {
            s[nn][0] = __expf(s[nn][0] - mn0);
            s[nn][1] = __expf(s[nn][1] - mn0);
            s[nn][2] = __expf(s[nn][2] - mn1);
            s[nn][3] = __expf(s[nn][3] - mn1);
            rs0 += s[nn][0] + s[nn][1];
            rs1 += s[nn][2] + s[nn][3];
        }
        rs0 += __shfl_xor_sync(0xffffffffu, rs0, 1);
        rs0 += __shfl_xor_sync(0xffffffffu, rs0, 2);
        rs1 += __shfl_xor_sync(0xffffffffu, rs1, 1);
        rs1 += __shfl_xor_sync(0xffffffffu, rs1, 2);
        lrow0 = lrow0 * alpha0 + rs0;
        lrow1 = lrow1 * alpha1 + rs1;

#pragma unroll
        for (int nn = 0; nn < 8; nn++) {
            o[nn][0] *= alpha0; o[nn][1] *= alpha0;
            o[nn][2] *= alpha1; o[nn][3] *= alpha1;
        }

        // O += P V : register-only P repack (validated ordering)
#pragma unroll
        for (int kp = 0; kp < 2; kp++) {
            uint32_t ae0 = pack_h2(s[4 * kp + 0][0], s[4 * kp + 0][1]);
            uint32_t ae1 = pack_h2(s[4 * kp + 0][2], s[4 * kp + 0][3]);
            uint32_t ae2 = pack_h2(s[4 * kp + 1][0], s[4 * kp + 1][1]);
            uint32_t ae3 = pack_h2(s[4 * kp + 1][2], s[4 * kp + 1][3]);
            uint32_t ao0 = pack_h2(s[4 * kp + 2][0], s[4 * kp + 2][1]);
            uint32_t ao1 = pack_h2(s[4 * kp + 2][2], s[4 * kp + 2][3]);
            uint32_t ao2 = pack_h2(s[4 * kp + 3][0], s[4 * kp + 3][1]);
            uint32_t ao3 = pack_h2(s[4 * kp + 3][2], s[4 * kp + 3][3]);
#pragma unroll
            for (int nn = 0; nn < 8; nn++) {
                uint4 Vv = *(const uint4*)&Vt[(nn * 8 + g) * GS + kp * 16 + 4 * t];
                mma_h(o[nn], ae0, ae1, ae2, ae3, Vv.x, Vv.y);
                mma_h(o[nn], ao0, ao1, ao2, ao3, Vv.z, Vv.w);
            }
        }
    }

    // finalize + store half perm16 directly
    const int b_ = bh >> 4;
    const int h  = bh & (HEADS - 1);
    const float inv0 = 1.f / lrow0;
    const float inv1 = 1.f / lrow1;
    const int tok0 = b_ * L_SEQ + q0 + qr0 + g;
    const int tok1 = tok0 + 8;
#pragma unroll
    for (int nn = 0; nn < 8; nn++) {
        int pos = h * 32 + ((nn >> 2) << 4) + 4 * t + (nn & 3);
        atth[(size_t)tok0 * 512 + pos] = pack_h2(o[nn][0] * inv0, o[nn][1] * inv0);
        atth[(size_t)tok1 * 512 + pos] = pack_h2(o[nn][2] * inv1, o[nn][3] * inv1);
    }
}

// ---------------------------------------------------------------------------
// Host launch
// ---------------------------------------------------------------------------
extern "C" void kernel_launch(void* const* d_in, const int* in_sizes, int n_in,
                              void* d_out, int out_size)
{
    const float* x       = (const float*)d_in[0];
    const float* w_qkv   = (const float*)d_in[1];
    const float* w_out   = (const float*)d_in[2];
    const float* q_scale = (const float*)d_in[3];
    const float* q_bias  = (const float*)d_in[4];
    const float* k_scale = (const float*)d_in[5];
    const float* k_bias  = (const float*)d_in[6];
    float* out = (float*)d_out;

    void *p_qkv, *p_qh, *p_kh, *p_vh, *p_vt, *p_xh, *p_wh, *p_worh, *p_atth;
    cudaGetSymbolAddress(&p_qkv, g_qkv);
    cudaGetSymbolAddress(&p_qh, g_qh);
    cudaGetSymbolAddress(&p_kh, g_kh);
    cudaGetSymbolAddress(&p_vh, g_vh);
    cudaGetSymbolAddress(&p_vt, g_vt);
    cudaGetSymbolAddress(&p_xh, g_xh);
    cudaGetSymbolAddress(&p_wh, g_wh);
    cudaGetSymbolAddress(&p_worh, g_worh);
    cudaGetSymbolAddress(&p_atth, g_atth);

    // 0) prep
    cvt_perm_kernel<<<(MTOT * 256 + 255) / 256, 256>>>(x, (uint32_t*)p_xh, MTOT * 256);
    transpose_cvt_perm_kernel<<<dim3(THREEC / 32, CDIM / 32), 256>>>(
        w_qkv, (uint32_t*)p_wh, CDIM, THREEC);
    transpose_cvt_perm_kernel<<<dim3(CDIM / 32, CDIM / 32), 256>>>(
        w_out, (uint32_t*)p_worh, CDIM, CDIM);

    // 1) QKV projection
    cudaFuncSetAttribute(gemm_h_kernel, cudaFuncAttributeMaxDynamicSharedMemorySize,
                         GEMM_SMEM_BYTES);
    gemm_h_kernel<<<dim3(THREEC / 128, MTOT / 128), 256, GEMM_SMEM_BYTES>>>(
        (const uint32_t*)p_xh, (const uint32_t*)p_wh, (float*)p_qkv, MTOT, THREEC);

    // 2) QK LayerNorm + split (q/k half perm16, v half natural)
    ln_split_h_kernel<<<(MTOT * HEADS) / 8, 256>>>(
        (const float*)p_qkv, q_scale, q_bias, k_scale, k_bias,
        (uint32_t*)p_qh, (uint32_t*)p_kh, (uint32_t*)p_vh);

    // 2b) V transpose (once per (b,h))
    transpose_v_kernel<<<dim3(L_SEQ / 64, BATCH * HEADS), 256>>>(
        (const uint32_t*)p_vh, (uint32_t*)p_vt);

    // 3) Flash attention -> half perm16 directly
    cudaFuncSetAttribute(attn_h2_kernel, cudaFuncAttributeMaxDynamicSharedMemorySize,
                         ATTN_SMEM_BYTES);
    attn_h2_kernel<<<dim3(L_SEQ / 128, BATCH * HEADS), 256, ATTN_SMEM_BYTES>>>(
        (const uint32_t*)p_qh, (const uint32_t*)p_kh, (const uint32_t*)p_vt,
        (uint32_t*)p_atth);

    // 4) Output projection
    gemm_h_kernel<<<dim3(CDIM / 128, MTOT / 128), 256, GEMM_SMEM_BYTES>>>(
        (const uint32_t*)p_atth, (const uint32_t*)p_worh, out, MTOT, CDIM);
}